// round 8
// baseline (speedup 1.0000x reference)
#include <cuda_runtime.h>
#include <cstdint>

#define B_  4
#define S_  2048
#define D_  1024
#define H_  16
#define DH_ 64
#define NSPLIT 8

// scratch
__device__ float g_qkv[(size_t)B_ * S_ * 3 * D_];   // [B*S, 3D]
__device__ float g_att[(size_t)B_ * S_ * D_];       // [B*S, D] scrambled, tf32-rounded
__device__ float g_Xr[(size_t)B_ * S_ * D_];        // tf32-rounded X
__device__ float g_W1r[(size_t)3 * D_ * D_];        // tf32-rounded W1
__device__ float g_W2r[(size_t)D_ * D_];            // tf32-rounded W2
__device__ float g_wp[(size_t)B_ * H_ * NSPLIT * 64 * 64]; // partial score tiles

// ---------------------------------------------------------------------------
__device__ __forceinline__ uint32_t s2u(const void* p) {
    return (uint32_t)__cvta_generic_to_shared(p);
}
__device__ __forceinline__ void cp16(uint32_t dst, const void* src) {
    asm volatile("cp.async.cg.shared.global [%0], [%1], 16;\n" :: "r"(dst), "l"(src));
}
__device__ __forceinline__ void cp_commit() {
    asm volatile("cp.async.commit_group;\n" ::: "memory");
}
__device__ __forceinline__ void cp_wait1() {
    asm volatile("cp.async.wait_group 1;\n" ::: "memory");
}
__device__ __forceinline__ float round_tf32(float v) {
    uint32_t r;
    asm("cvt.rna.tf32.f32 %0, %1;\n" : "=r"(r) : "f"(v));
    return __uint_as_float(r);
}
__device__ __forceinline__ void mma_tf32(
    float& c0, float& c1, float& c2, float& c3,
    float a0, float a1, float a2, float a3,
    float b0, float b1)
{
    asm volatile(
        "mma.sync.aligned.m16n8k8.row.col.f32.tf32.tf32.f32 "
        "{%0,%1,%2,%3}, {%4,%5,%6,%7}, {%8,%9}, {%0,%1,%2,%3};\n"
        : "+f"(c0), "+f"(c1), "+f"(c2), "+f"(c3)
        : "r"(__float_as_uint(a0)), "r"(__float_as_uint(a1)),
          "r"(__float_as_uint(a2)), "r"(__float_as_uint(a3)),
          "r"(__float_as_uint(b0)), "r"(__float_as_uint(b1)));
}

// ---------------------------------------------------------------------------
// Pre-round inputs to tf32 (rna)
// ---------------------------------------------------------------------------
#define NX   (B_ * S_ * D_ / 4)
#define NW1  (3 * D_ * D_ / 4)
#define NW2  (D_ * D_ / 4)

__global__ void __launch_bounds__(256) round_inputs(
    const float4* __restrict__ X, const float4* __restrict__ W1,
    const float4* __restrict__ W2, float4* __restrict__ Xr,
    float4* __restrict__ W1r, float4* __restrict__ W2r)
{
    int i = blockIdx.x * blockDim.x + threadIdx.x;
    const float4* src; float4* dst; int idx;
    if (i < NX)            { src = X;  dst = Xr;  idx = i; }
    else if (i < NX + NW1) { src = W1; dst = W1r; idx = i - NX; }
    else if (i < NX + NW1 + NW2) { src = W2; dst = W2r; idx = i - NX - NW1; }
    else return;
    float4 v = src[idx];
    v.x = round_tf32(v.x); v.y = round_tf32(v.y);
    v.z = round_tf32(v.z); v.w = round_tf32(v.w);
    dst[idx] = v;
}

// ---------------------------------------------------------------------------
// tf32 mma.sync GEMM (NT): C = A @ W^T + bias. Inputs pre-rounded.
// CTA 128x128, 128 threads (4 warps, 2x2, warp tile 64x64), BK=32,
// 3-stage cp.async, 2 CTAs/SM (96 KB smem each).
// ---------------------------------------------------------------------------
#define TM 128
#define TN 128
#define TK 32
#define NSTAGE 3
#define A_FLOATS (128 * 32)
#define B_FLOATS (128 * 32)
#define GEMM_SMEM (NSTAGE * (A_FLOATS + B_FLOATS) * 4)   // 96 KB

__global__ void __launch_bounds__(128, 2) gemm_mma(
    const float* __restrict__ A, const float* __restrict__ W,
    const float* __restrict__ bias, float* __restrict__ C,
    int M, int N, int K)
{
    extern __shared__ float smem[];
    float* As = smem;                           // [NSTAGE][4096]
    float* Bs = smem + NSTAGE * A_FLOATS;       // [NSTAGE][4096]
    const uint32_t sA0 = s2u(As);
    const uint32_t sB0 = s2u(Bs);

    const int tid = threadIdx.x;
    const int wid = tid >> 5;
    const int lid = tid & 31;
    const int wm  = wid & 1;          // 2 warp rows -> 64 M
    const int wn  = wid >> 1;         // 2 warp cols -> 64 N
    const int g   = lid >> 2;
    const int t   = lid & 3;
    const int bm  = blockIdx.y * TM;
    const int bn  = blockIdx.x * TN;

    const int lrow = tid >> 3;        // 0..15
    const int lc4  = tid & 7;
    const uint32_t ldst = ((uint32_t)(lc4 ^ (lrow & 7))) * 16;

    float acc[4][8][4];
#pragma unroll
    for (int i = 0; i < 4; i++)
#pragma unroll
        for (int j = 0; j < 8; j++)
#pragma unroll
            for (int q = 0; q < 4; q++) acc[i][j][q] = 0.f;

    const int NCHUNK = K / TK;

#pragma unroll
    for (int p = 0; p < NSTAGE - 1; p++) {
        const float* Ag = A + (size_t)(bm + lrow) * K + p * TK + lc4 * 4;
        const float* Wg = W + (size_t)(bn + lrow) * K + p * TK + lc4 * 4;
        uint32_t dA = sA0 + p * (A_FLOATS * 4) + lrow * 128 + ldst;
        uint32_t dB = sB0 + p * (B_FLOATS * 4) + lrow * 128 + ldst;
#pragma unroll
        for (int r = 0; r < 8; r++) {
            cp16(dA + r * (16 * 128), Ag + (size_t)(r * 16) * K);
            cp16(dB + r * (16 * 128), Wg + (size_t)(r * 16) * K);
        }
        cp_commit();
    }

    const int swz = g << 2;

    for (int kc = 0; kc < NCHUNK; kc++) {
        cp_wait1();
        __syncthreads();

        const int s = kc % NSTAGE;
        const uint32_t* as = (const uint32_t*)(As + s * A_FLOATS + (wm * 64 + g) * 32);
        const uint32_t* bs = (const uint32_t*)(Bs + s * B_FLOATS + (wn * 64 + g) * 32);

#pragma unroll
        for (int kk = 0; kk < 4; kk++) {
            const int k0 = kk * 8;
            const int ck0 = (k0 + t) ^ swz;
            const int ck1 = (k0 + t + 4) ^ swz;

            uint32_t af[4][4];
#pragma unroll
            for (int i = 0; i < 4; i++) {
                const uint32_t* ai = as + i * (16 * 32);
                af[i][0] = ai[ck0];
                af[i][1] = ai[8 * 32 + ck0];
                af[i][2] = ai[ck1];
                af[i][3] = ai[8 * 32 + ck1];
            }
            uint32_t bf[8][2];
#pragma unroll
            for (int j = 0; j < 8; j++) {
                const uint32_t* bj = bs + j * (8 * 32);
                bf[j][0] = bj[ck0];
                bf[j][1] = bj[ck1];
            }
#pragma unroll
            for (int i = 0; i < 4; i++)
#pragma unroll
                for (int j = 0; j < 8; j++)
                    mma_tf32(acc[i][j][0], acc[i][j][1], acc[i][j][2], acc[i][j][3],
                             __uint_as_float(af[i][0]), __uint_as_float(af[i][1]),
                             __uint_as_float(af[i][2]), __uint_as_float(af[i][3]),
                             __uint_as_float(bf[j][0]), __uint_as_float(bf[j][1]));
        }

        const int nk = kc + NSTAGE - 1;
        if (nk < NCHUNK) {
            const int sn = nk % NSTAGE;
            const float* Ag = A + (size_t)(bm + lrow) * K + nk * TK + lc4 * 4;
            const float* Wg = W + (size_t)(bn + lrow) * K + nk * TK + lc4 * 4;
            uint32_t dA = sA0 + sn * (A_FLOATS * 4) + lrow * 128 + ldst;
            uint32_t dB = sB0 + sn * (B_FLOATS * 4) + lrow * 128 + ldst;
#pragma unroll
            for (int r = 0; r < 8; r++) {
                cp16(dA + r * (16 * 128), Ag + (size_t)(r * 16) * K);
                cp16(dB + r * (16 * 128), Wg + (size_t)(r * 16) * K);
            }
        }
        cp_commit();
    }

    // epilogue
#pragma unroll
    for (int i = 0; i < 4; i++) {
        const int row0 = bm + wm * 64 + i * 16 + g;
#pragma unroll
        for (int j = 0; j < 8; j++) {
            const int col = bn + wn * 64 + j * 8 + 2 * t;
            const float b0 = bias[col];
            const float b1 = bias[col + 1];
            float2 v0 = make_float2(acc[i][j][0] + b0, acc[i][j][1] + b1);
            float2 v1 = make_float2(acc[i][j][2] + b0, acc[i][j][3] + b1);
            *(float2*)&C[(size_t)row0 * N + col] = v0;
            *(float2*)&C[(size_t)(row0 + 8) * N + col] = v1;
        }
    }
}

// ---------------------------------------------------------------------------
// Attention stage A (tensor): partial scores. grid (64, NSPLIT).
// ---------------------------------------------------------------------------
#define PAD 68

__global__ void __launch_bounds__(256) attn_scores(
    const float* __restrict__ qkv, float* __restrict__ wp)
{
    __shared__ float sm[2 * 64 * PAD];
    float* S0 = sm;                 // Q chunk [s][d], tf32-rounded
    float* S1 = sm + 64 * PAD;      // K chunk [s][e], tf32-rounded

    const int bh = blockIdx.x;
    const int split = blockIdx.y;
    const int b  = bh >> 4;
    const int h  = bh & 15;
    const float* base = qkv + (size_t)b * S_ * (3 * D_);

    const int tid = threadIdx.x;
    const int wid = tid >> 5;
    const int lid = tid & 31;
    const int g   = lid >> 2;
    const int t   = lid & 3;
    const int wm  = wid & 3;        // 4 m-blocks of 16 -> 64 d
    const int wn  = wid >> 2;       // 2 n-blocks of 32 -> 64 e
    const int dA  = wm * 16 + g;
    const int nB  = wn * 32 + g;

    float acc[4][4];
#pragma unroll
    for (int j = 0; j < 4; j++)
#pragma unroll
        for (int q = 0; q < 4; q++) acc[j][q] = 0.f;

    const int sbeg = split * (S_ / NSPLIT);
    for (int s0 = sbeg; s0 < sbeg + S_ / NSPLIT; s0 += 64) {
#pragma unroll
        for (int jj = 0; jj < 4; jj++) {
            int l  = tid + jj * 256;
            int ss = l >> 4;
            int c4 = (l & 15) * 4;
            const float* gp = base + (size_t)(s0 + ss) * (3 * D_) + h * DH_ + c4;
            float4 q = *(const float4*)gp;
            float4 k = *(const float4*)(gp + D_);
            q.x = round_tf32(q.x); q.y = round_tf32(q.y);
            q.z = round_tf32(q.z); q.w = round_tf32(q.w);
            k.x = round_tf32(k.x); k.y = round_tf32(k.y);
            k.z = round_tf32(k.z); k.w = round_tf32(k.w);
            *(float4*)&S0[ss * PAD + c4] = q;
            *(float4*)&S1[ss * PAD + c4] = k;
        }
        __syncthreads();

#pragma unroll
        for (int ko = 0; ko < 8; ko++) {
            const int kr = ko * 8 + t;          // s index (contraction)
            float a0 = S0[kr * PAD + dA];
            float a1 = S0[kr * PAD + dA + 8];
            float a2 = S0[(kr + 4) * PAD + dA];
            float a3 = S0[(kr + 4) * PAD + dA + 8];
#pragma unroll
            for (int j = 0; j < 4; j++) {
                float b0 = S1[kr * PAD + nB + j * 8];
                float b1 = S1[(kr + 4) * PAD + nB + j * 8];
                mma_tf32(acc[j][0], acc[j][1], acc[j][2], acc[j][3],
                         a0, a1, a2, a3, b0, b1);
            }
        }
        __syncthreads();
    }

    float* wt = wp + ((size_t)(bh * NSPLIT + split)) * 4096;
    const int col0 = wn * 32 + 2 * t;
#pragma unroll
    for (int j = 0; j < 4; j++) {
        *(float2*)&wt[dA * 64 + col0 + j * 8]       = make_float2(acc[j][0], acc[j][1]);
        *(float2*)&wt[(dA + 8) * 64 + col0 + j * 8] = make_float2(acc[j][2], acc[j][3]);
    }
}

// ---------------------------------------------------------------------------
// Attention stage B (tensor): reduce partials + softmax + o = w @ V,
// scrambled tf32-rounded store. grid (64, NSPLIT).
// ---------------------------------------------------------------------------
__global__ void __launch_bounds__(256) attn_out(
    const float* __restrict__ qkv, const float* __restrict__ wp,
    float* __restrict__ out)
{
    __shared__ float sm[2 * 64 * PAD];
    float* S0 = sm;                 // w
    float* S1 = sm + 64 * PAD;      // V stage

    const int bh = blockIdx.x;
    const int split = blockIdx.y;
    const int b  = bh >> 4;
    const int h  = bh & 15;
    const float* base = qkv + (size_t)b * S_ * (3 * D_);
    const float* wt = wp + (size_t)bh * NSPLIT * 4096;

    const int tid = threadIdx.x;
    const int wid = tid >> 5;
    const int lid = tid & 31;
    const int g   = lid >> 2;
    const int t   = lid & 3;
    const int wm  = wid & 3;        // 4 m-blocks of 16 -> 64 d
    const int wn  = wid >> 2;       // 2 n-blocks of 32 -> 64 s per chunk
    const float scale = rsqrtf((float)S_);

    // reduce NSPLIT partials into S0 (w), scaled
    for (int l = tid; l < 1024; l += 256) {
        int d  = l >> 4;
        int e4 = (l & 15) * 4;
        float4 r = make_float4(0.f, 0.f, 0.f, 0.f);
#pragma unroll
        for (int p = 0; p < NSPLIT; p++) {
            float4 q = *(const float4*)&wt[(size_t)p * 4096 + d * 64 + e4];
            r.x += q.x; r.y += q.y; r.z += q.z; r.w += q.w;
        }
        r.x *= scale; r.y *= scale; r.z *= scale; r.w *= scale;
        *(float4*)&S0[d * PAD + e4] = r;
    }
    __syncthreads();

    // softmax rows (fp32), round result to tf32 in place
    if (tid < 64) {
        float* row = &S0[tid * PAD];
        float m = -1e30f;
#pragma unroll
        for (int e = 0; e < 64; e++) m = fmaxf(m, row[e]);
        float s = 0.f;
#pragma unroll
        for (int e = 0; e < 64; e++) { float v = expf(row[e] - m); row[e] = v; s += v; }
        float inv = 1.f / s;
#pragma unroll
        for (int e = 0; e < 64; e++) row[e] = round_tf32(row[e] * inv);
    }
    __syncthreads();

    // hoist w fragments (constant across chunks): 32 regs
    float aw[8][4];
#pragma unroll
    for (int ko = 0; ko < 8; ko++) {
        const int kr = ko * 8 + t;              // e index (contraction)
        aw[ko][0] = S0[(wm * 16 + g) * PAD + kr];
        aw[ko][1] = S0[(wm * 16 + g + 8) * PAD + kr];
        aw[ko][2] = S0[(wm * 16 + g) * PAD + kr + 4];
        aw[ko][3] = S0[(wm * 16 + g + 8) * PAD + kr + 4];
    }

    const int sbeg = split * (S_ / NSPLIT);
    const int d  = wm * 16 + g;
    const int sl = wn * 32 + 2 * t;

    for (int s0 = sbeg; s0 < sbeg + S_ / NSPLIT; s0 += 64) {
#pragma unroll
        for (int jj = 0; jj < 4; jj++) {
            int l  = tid + jj * 256;
            int ss = l >> 4;
            int e4 = (l & 15) * 4;
            float4 v = *(const float4*)(base + (size_t)(s0 + ss) * (3 * D_) + 2 * D_ + h * DH_ + e4);
            v.x = round_tf32(v.x); v.y = round_tf32(v.y);
            v.z = round_tf32(v.z); v.w = round_tf32(v.w);
            *(float4*)&S1[ss * PAD + e4] = v;
        }
        __syncthreads();

        float acc[4][4];
#pragma unroll
        for (int j = 0; j < 4; j++)
#pragma unroll
            for (int q = 0; q < 4; q++) acc[j][q] = 0.f;

#pragma unroll
        for (int ko = 0; ko < 8; ko++) {
            const int kr = ko * 8 + t;
#pragma unroll
            for (int j = 0; j < 4; j++) {
                const float* vr = &S1[(wn * 32 + j * 8 + g) * PAD];
                float b0 = vr[kr];
                float b1 = vr[kr + 4];
                mma_tf32(acc[j][0], acc[j][1], acc[j][2], acc[j][3],
                         aw[ko][0], aw[ko][1], aw[ko][2], aw[ko][3], b0, b1);
            }
        }
        __syncthreads();

        // scrambled store: out[b][h*128 + 2d + (s>>10)][s & 1023]
#pragma unroll
        for (int j = 0; j < 4; j++) {
            int s = s0 + sl + j * 8;
            int col = s & 1023;
            int hi  = s >> 10;
            size_t r0 = ((size_t)b * S_ + h * 128 + d * 2 + hi) * D_ + col;
            size_t r1 = ((size_t)b * S_ + h * 128 + (d + 8) * 2 + hi) * D_ + col;
            *(float2*)&out[r0] = make_float2(round_tf32(acc[j][0]), round_tf32(acc[j][1]));
            *(float2*)&out[r1] = make_float2(round_tf32(acc[j][2]), round_tf32(acc[j][3]));
        }
    }
}

// ---------------------------------------------------------------------------
extern "C" void kernel_launch(void* const* d_in, const int* in_sizes, int n_in,
                              void* d_out, int out_size)
{
    const float* X  = (const float*)d_in[0];
    const float* W1 = (const float*)d_in[1];
    const float* b1 = (const float*)d_in[2];
    const float* W2 = (const float*)d_in[3];
    const float* b2 = (const float*)d_in[4];
    float* out = (float*)d_out;

    float *qkv, *att, *Xr, *W1r, *W2r, *wp;
    cudaGetSymbolAddress((void**)&qkv, g_qkv);
    cudaGetSymbolAddress((void**)&att, g_att);
    cudaGetSymbolAddress((void**)&Xr,  g_Xr);
    cudaGetSymbolAddress((void**)&W1r, g_W1r);
    cudaGetSymbolAddress((void**)&W2r, g_W2r);
    cudaGetSymbolAddress((void**)&wp,  g_wp);

    cudaFuncSetAttribute(gemm_mma, cudaFuncAttributeMaxDynamicSharedMemorySize, GEMM_SMEM);

    // 0) pre-round inputs to tf32
    int total4 = NX + NW1 + NW2;
    round_inputs<<<(total4 + 255) / 256, 256>>>(
        (const float4*)X, (const float4*)W1, (const float4*)W2,
        (float4*)Xr, (float4*)W1r, (float4*)W2r);

    // 1) GEMM1: QKV = Xr @ W1r^T + b1   [8192, 3072]
    dim3 g1(3 * D_ / TN, (B_ * S_) / TM);
    gemm_mma<<<g1, 128, GEMM_SMEM>>>(Xr, W1r, b1, qkv, B_ * S_, 3 * D_, D_);

    // 2) attention (tensor-core)
    attn_scores<<<dim3(B_ * H_, NSPLIT), 256>>>(qkv, wp);
    attn_out<<<dim3(B_ * H_, NSPLIT), 256>>>(qkv, wp, att);

    // 3) GEMM3: out = att @ W2r^T + b2  [8192, 1024]
    dim3 g3(D_ / TN, (B_ * S_) / TM);
    gemm_mma<<<g3, 128, GEMM_SMEM>>>(att, W2r, b2, out, B_ * S_, D_, D_);
}

// round 11
// speedup vs baseline: 1.1876x; 1.1876x over previous
#include <cuda_runtime.h>
#include <cstdint>

#define B_  4
#define S_  2048
#define D_  1024
#define H_  16
#define DH_ 64
#define NSPLIT 8

// scratch
__device__ float g_qkv[(size_t)B_ * S_ * 3 * D_];   // [B*S, 3D]
__device__ float g_att[(size_t)B_ * S_ * D_];       // [B*S, D] scrambled+K-permuted, tf32
__device__ float g_Xr[(size_t)B_ * S_ * D_];        // tf32-rounded, K-permuted X
__device__ float g_W1r[(size_t)3 * D_ * D_];        // tf32-rounded, K-permuted W1
__device__ float g_W2r[(size_t)D_ * D_];            // tf32-rounded, K-permuted W2
__device__ float g_wp[(size_t)B_ * H_ * NSPLIT * 64 * 64]; // partial score tiles

// ---------------------------------------------------------------------------
__device__ __forceinline__ uint32_t s2u(const void* p) {
    return (uint32_t)__cvta_generic_to_shared(p);
}
__device__ __forceinline__ void cp16(uint32_t dst, const void* src) {
    asm volatile("cp.async.cg.shared.global [%0], [%1], 16;\n" :: "r"(dst), "l"(src));
}
__device__ __forceinline__ void cp_commit() {
    asm volatile("cp.async.commit_group;\n" ::: "memory");
}
__device__ __forceinline__ void cp_wait1() {
    asm volatile("cp.async.wait_group 1;\n" ::: "memory");
}
__device__ __forceinline__ float round_tf32(float v) {
    uint32_t r;
    asm("cvt.rna.tf32.f32 %0, %1;\n" : "=r"(r) : "f"(v));
    return __uint_as_float(r);
}
__device__ __forceinline__ void mma_tf32(
    float& c0, float& c1, float& c2, float& c3,
    float a0, float a1, float a2, float a3,
    float b0, float b1)
{
    asm volatile(
        "mma.sync.aligned.m16n8k8.row.col.f32.tf32.tf32.f32 "
        "{%0,%1,%2,%3}, {%4,%5,%6,%7}, {%8,%9}, {%0,%1,%2,%3};\n"
        : "+f"(c0), "+f"(c1), "+f"(c2), "+f"(c3)
        : "r"(__float_as_uint(a0)), "r"(__float_as_uint(a1)),
          "r"(__float_as_uint(a2)), "r"(__float_as_uint(a3)),
          "r"(__float_as_uint(b0)), "r"(__float_as_uint(b1)));
}

// ---------------------------------------------------------------------------
// Pre-round inputs to tf32 (rna) AND permute K within 8-blocks:
// phys p gets logical k where p(k) = (k&~7) | 2*(k&3) | ((k>>2)&1).
// Each thread handles one 8-float block (2 float4 in, 2 float4 out).
// ---------------------------------------------------------------------------
#define NX   (B_ * S_ * D_ / 4)
#define NW1  (3 * D_ * D_ / 4)
#define NW2  (D_ * D_ / 4)
#define TOT8 ((NX + NW1 + NW2) / 2)

__global__ void __launch_bounds__(256) round_inputs(
    const float4* __restrict__ X, const float4* __restrict__ W1,
    const float4* __restrict__ W2, float4* __restrict__ Xr,
    float4* __restrict__ W1r, float4* __restrict__ W2r)
{
    int i = blockIdx.x * blockDim.x + threadIdx.x;
    if (i >= TOT8) return;
    int q = 2 * i;
    const float4* src; float4* dst; int idx;
    if (q < NX)            { src = X;  dst = Xr;  idx = q; }
    else if (q < NX + NW1) { src = W1; dst = W1r; idx = q - NX; }
    else                   { src = W2; dst = W2r; idx = q - NX - NW1; }
    float4 lo = src[idx];       // k0..k3
    float4 hi = src[idx + 1];   // k4..k7
    lo.x = round_tf32(lo.x); lo.y = round_tf32(lo.y);
    lo.z = round_tf32(lo.z); lo.w = round_tf32(lo.w);
    hi.x = round_tf32(hi.x); hi.y = round_tf32(hi.y);
    hi.z = round_tf32(hi.z); hi.w = round_tf32(hi.w);
    dst[idx]     = make_float4(lo.x, hi.x, lo.y, hi.y);  // p0..p3 = k0,k4,k1,k5
    dst[idx + 1] = make_float4(lo.z, hi.z, lo.w, hi.w);  // p4..p7 = k2,k6,k3,k7
}

// ---------------------------------------------------------------------------
// tf32 mma.sync GEMM (NT): C = A @ W^T + bias. Inputs pre-rounded + K-permuted.
// CTA 128x256, warp 64x64, BK=32, 3-stage cp.async, LDS.64 fragment loads.
// ---------------------------------------------------------------------------
#define TM 128
#define TN 256
#define TK 32
#define NSTAGE 3
#define A_FLOATS (128 * 32)
#define B_FLOATS (256 * 32)
#define GEMM_SMEM (NSTAGE * (A_FLOATS + B_FLOATS) * 4)   // 144 KB

__global__ void __launch_bounds__(256, 1) gemm_mma(
    const float* __restrict__ A, const float* __restrict__ W,
    const float* __restrict__ bias, float* __restrict__ C,
    int M, int N, int K)
{
    extern __shared__ float smem[];
    float* As = smem;                           // [NSTAGE][4096]
    float* Bs = smem + NSTAGE * A_FLOATS;       // [NSTAGE][8192]
    const uint32_t sA0 = s2u(As);
    const uint32_t sB0 = s2u(Bs);

    const int tid = threadIdx.x;
    const int wid = tid >> 5;
    const int lid = tid & 31;
    const int wm  = wid & 1;          // 2 warp rows -> 64 M
    const int wn  = wid >> 1;         // 4 warp cols -> 64 N
    const int g   = lid >> 2;
    const int t   = lid & 3;
    const int bm  = blockIdx.y * TM;
    const int bn  = blockIdx.x * TN;

    const int lrow = tid >> 3;        // 0..31
    const int lc4  = tid & 7;
    const uint32_t ldst = ((uint32_t)(lc4 ^ (lrow & 7))) * 16;

    float acc[4][8][4];
#pragma unroll
    for (int i = 0; i < 4; i++)
#pragma unroll
        for (int j = 0; j < 8; j++)
#pragma unroll
            for (int q = 0; q < 4; q++) acc[i][j][q] = 0.f;

    const int NCHUNK = K / TK;

#pragma unroll
    for (int p = 0; p < NSTAGE - 1; p++) {
        const float* Ag = A + (size_t)(bm + lrow) * K + p * TK + lc4 * 4;
        const float* Wg = W + (size_t)(bn + lrow) * K + p * TK + lc4 * 4;
        uint32_t dA = sA0 + p * (A_FLOATS * 4) + lrow * 128 + ldst;
        uint32_t dB = sB0 + p * (B_FLOATS * 4) + lrow * 128 + ldst;
#pragma unroll
        for (int r = 0; r < 4; r++)
            cp16(dA + r * (32 * 128), Ag + (size_t)(r * 32) * K);
#pragma unroll
        for (int r = 0; r < 8; r++)
            cp16(dB + r * (32 * 128), Wg + (size_t)(r * 32) * K);
        cp_commit();
    }

    for (int kc = 0; kc < NCHUNK; kc++) {
        cp_wait1();
        __syncthreads();

        const int s = kc % NSTAGE;
        const char* aw = (const char*)(As + s * A_FLOATS + (wm * 64 + g) * 32);
        const char* bw = (const char*)(Bs + s * B_FLOATS + (wn * 64 + g) * 32);

#pragma unroll
        for (int kk = 0; kk < 4; kk++) {
            const int phys = kk * 8 + 2 * t;                 // permuted k pair start
            const uint32_t off = ((((phys >> 2) ^ g) << 4) | ((phys & 3) << 2));

            float2 aLo[4], aHi[4];
#pragma unroll
            for (int i = 0; i < 4; i++) {
                aLo[i] = *(const float2*)(aw + i * (16 * 128) + off);            // (a0,a2)
                aHi[i] = *(const float2*)(aw + i * (16 * 128) + 8 * 128 + off);  // (a1,a3)
            }
            float2 bv[8];
#pragma unroll
            for (int j = 0; j < 8; j++)
                bv[j] = *(const float2*)(bw + j * (8 * 128) + off);              // (b0,b1)

#pragma unroll
            for (int i = 0; i < 4; i++)
#pragma unroll
                for (int j = 0; j < 8; j++)
                    mma_tf32(acc[i][j][0], acc[i][j][1], acc[i][j][2], acc[i][j][3],
                             aLo[i].x, aHi[i].x, aLo[i].y, aHi[i].y,
                             bv[j].x, bv[j].y);
        }

        const int nk = kc + NSTAGE - 1;
        if (nk < NCHUNK) {
            const int sn = nk % NSTAGE;
            const float* Ag = A + (size_t)(bm + lrow) * K + nk * TK + lc4 * 4;
            const float* Wg = W + (size_t)(bn + lrow) * K + nk * TK + lc4 * 4;
            uint32_t dA = sA0 + sn * (A_FLOATS * 4) + lrow * 128 + ldst;
            uint32_t dB = sB0 + sn * (B_FLOATS * 4) + lrow * 128 + ldst;
#pragma unroll
            for (int r = 0; r < 4; r++)
                cp16(dA + r * (32 * 128), Ag + (size_t)(r * 32) * K);
#pragma unroll
            for (int r = 0; r < 8; r++)
                cp16(dB + r * (32 * 128), Wg + (size_t)(r * 32) * K);
        }
        cp_commit();
    }

    // epilogue
#pragma unroll
    for (int i = 0; i < 4; i++) {
        const int row0 = bm + wm * 64 + i * 16 + g;
#pragma unroll
        for (int j = 0; j < 8; j++) {
            const int col = bn + wn * 64 + j * 8 + 2 * t;
            const float b0 = bias[col];
            const float b1 = bias[col + 1];
            float2 v0 = make_float2(acc[i][j][0] + b0, acc[i][j][1] + b1);
            float2 v1 = make_float2(acc[i][j][2] + b0, acc[i][j][3] + b1);
            *(float2*)&C[(size_t)row0 * N + col] = v0;
            *(float2*)&C[(size_t)(row0 + 8) * N + col] = v1;
        }
    }
}

// ---------------------------------------------------------------------------
// Attention stage A (tensor): partial scores. grid (64, NSPLIT).  (R7 proven)
// ---------------------------------------------------------------------------
#define PAD 68

__global__ void __launch_bounds__(256) attn_scores(
    const float* __restrict__ qkv, float* __restrict__ wp)
{
    __shared__ float sm[2 * 64 * PAD];
    float* S0 = sm;                 // Q chunk [s][d], tf32-rounded
    float* S1 = sm + 64 * PAD;      // K chunk [s][e], tf32-rounded

    const int bh = blockIdx.x;
    const int split = blockIdx.y;
    const int b  = bh >> 4;
    const int h  = bh & 15;
    const float* base = qkv + (size_t)b * S_ * (3 * D_);

    const int tid = threadIdx.x;
    const int wid = tid >> 5;
    const int lid = tid & 31;
    const int g   = lid >> 2;
    const int t   = lid & 3;
    const int wm  = wid & 3;        // 4 m-blocks of 16 -> 64 d
    const int wn  = wid >> 2;       // 2 n-blocks of 32 -> 64 e
    const int dA  = wm * 16 + g;
    const int nB  = wn * 32 + g;

    float acc[4][4];
#pragma unroll
    for (int j = 0; j < 4; j++)
#pragma unroll
        for (int q = 0; q < 4; q++) acc[j][q] = 0.f;

    const int sbeg = split * (S_ / NSPLIT);
    for (int s0 = sbeg; s0 < sbeg + S_ / NSPLIT; s0 += 64) {
#pragma unroll
        for (int jj = 0; jj < 4; jj++) {
            int l  = tid + jj * 256;
            int ss = l >> 4;
            int c4 = (l & 15) * 4;
            const float* gp = base + (size_t)(s0 + ss) * (3 * D_) + h * DH_ + c4;
            float4 q = *(const float4*)gp;
            float4 k = *(const float4*)(gp + D_);
            q.x = round_tf32(q.x); q.y = round_tf32(q.y);
            q.z = round_tf32(q.z); q.w = round_tf32(q.w);
            k.x = round_tf32(k.x); k.y = round_tf32(k.y);
            k.z = round_tf32(k.z); k.w = round_tf32(k.w);
            *(float4*)&S0[ss * PAD + c4] = q;
            *(float4*)&S1[ss * PAD + c4] = k;
        }
        __syncthreads();

#pragma unroll
        for (int ko = 0; ko < 8; ko++) {
            const int kr = ko * 8 + t;          // s index (contraction)
            float a0 = S0[kr * PAD + dA];
            float a1 = S0[kr * PAD + dA + 8];
            float a2 = S0[(kr + 4) * PAD + dA];
            float a3 = S0[(kr + 4) * PAD + dA + 8];
#pragma unroll
            for (int j = 0; j < 4; j++) {
                float b0 = S1[kr * PAD + nB + j * 8];
                float b1 = S1[(kr + 4) * PAD + nB + j * 8];
                mma_tf32(acc[j][0], acc[j][1], acc[j][2], acc[j][3],
                         a0, a1, a2, a3, b0, b1);
            }
        }
        __syncthreads();
    }

    float* wt = wp + ((size_t)(bh * NSPLIT + split)) * 4096;
    const int col0 = wn * 32 + 2 * t;
#pragma unroll
    for (int j = 0; j < 4; j++) {
        *(float2*)&wt[dA * 64 + col0 + j * 8]       = make_float2(acc[j][0], acc[j][1]);
        *(float2*)&wt[(dA + 8) * 64 + col0 + j * 8] = make_float2(acc[j][2], acc[j][3]);
    }
}

// ---------------------------------------------------------------------------
// Attention stage B (tensor): reduce partials + softmax + o = w @ V,
// scrambled + K-permuted tf32 store (feeds GEMM3). grid (64, NSPLIT).
// ---------------------------------------------------------------------------
__global__ void __launch_bounds__(256) attn_out(
    const float* __restrict__ qkv, const float* __restrict__ wp,
    float* __restrict__ out)
{
    __shared__ float sm[2 * 64 * PAD];
    float* S0 = sm;                 // w
    float* S1 = sm + 64 * PAD;      // V stage

    const int bh = blockIdx.x;
    const int split = blockIdx.y;
    const int b  = bh >> 4;
    const int h  = bh & 15;
    const float* base = qkv + (size_t)b * S_ * (3 * D_);
    const float* wt = wp + (size_t)bh * NSPLIT * 4096;

    const int tid = threadIdx.x;
    const int wid = tid >> 5;
    const int lid = tid & 31;
    const int g   = lid >> 2;
    const int t   = lid & 3;
    const int wm  = wid & 3;        // 4 m-blocks of 16 -> 64 d
    const int wn  = wid >> 2;       // 2 n-blocks of 32 -> 64 s per chunk
    const float scale = rsqrtf((float)S_);

    // reduce NSPLIT partials into S0 (w), scaled
    for (int l = tid; l < 1024; l += 256) {
        int d  = l >> 4;
        int e4 = (l & 15) * 4;
        float4 r = make_float4(0.f, 0.f, 0.f, 0.f);
#pragma unroll
        for (int p = 0; p < NSPLIT; p++) {
            float4 q = *(const float4*)&wt[(size_t)p * 4096 + d * 64 + e4];
            r.x += q.x; r.y += q.y; r.z += q.z; r.w += q.w;
        }
        r.x *= scale; r.y *= scale; r.z *= scale; r.w *= scale;
        *(float4*)&S0[d * PAD + e4] = r;
    }
    __syncthreads();

    // softmax rows (fp32), round result to tf32 in place
    if (tid < 64) {
        float* row = &S0[tid * PAD];
        float m = -1e30f;
#pragma unroll
        for (int e = 0; e < 64; e++) m = fmaxf(m, row[e]);
        float s = 0.f;
#pragma unroll
        for (int e = 0; e < 64; e++) { float v = expf(row[e] - m); row[e] = v; s += v; }
        float inv = 1.f / s;
#pragma unroll
        for (int e = 0; e < 64; e++) row[e] = round_tf32(row[e] * inv);
    }
    __syncthreads();

    // hoist w fragments (constant across chunks): 32 regs
    float aw[8][4];
#pragma unroll
    for (int ko = 0; ko < 8; ko++) {
        const int kr = ko * 8 + t;              // e index (contraction)
        aw[ko][0] = S0[(wm * 16 + g) * PAD + kr];
        aw[ko][1] = S0[(wm * 16 + g + 8) * PAD + kr];
        aw[ko][2] = S0[(wm * 16 + g) * PAD + kr + 4];
        aw[ko][3] = S0[(wm * 16 + g + 8) * PAD + kr + 4];
    }

    const int sbeg = split * (S_ / NSPLIT);
    const int d  = wm * 16 + g;
    const int sl = wn * 32 + 2 * t;

    for (int s0 = sbeg; s0 < sbeg + S_ / NSPLIT; s0 += 64) {
#pragma unroll
        for (int jj = 0; jj < 4; jj++) {
            int l  = tid + jj * 256;
            int ss = l >> 4;
            int e4 = (l & 15) * 4;
            float4 v = *(const float4*)(base + (size_t)(s0 + ss) * (3 * D_) + 2 * D_ + h * DH_ + e4);
            v.x = round_tf32(v.x); v.y = round_tf32(v.y);
            v.z = round_tf32(v.z); v.w = round_tf32(v.w);
            *(float4*)&S1[ss * PAD + e4] = v;
        }
        __syncthreads();

        float acc[4][4];
#pragma unroll
        for (int j = 0; j < 4; j++)
#pragma unroll
            for (int q = 0; q < 4; q++) acc[j][q] = 0.f;

#pragma unroll
        for (int ko = 0; ko < 8; ko++) {
            const int kr = ko * 8 + t;
#pragma unroll
            for (int j = 0; j < 4; j++) {
                const float* vr = &S1[(wn * 32 + j * 8 + g) * PAD];
                float b0 = vr[kr];
                float b1 = vr[kr + 4];
                mma_tf32(acc[j][0], acc[j][1], acc[j][2], acc[j][3],
                         aw[ko][0], aw[ko][1], aw[ko][2], aw[ko][3], b0, b1);
            }
        }
        __syncthreads();

        // scrambled store with K-permutation for GEMM3:
        // logical col c -> phys (c&~7) | 2*(c&3) | ((c&4)>>2)
#pragma unroll
        for (int j = 0; j < 4; j++) {
            int s = s0 + sl + j * 8;
            int c  = s & 1023;          // even, c&7 in {0,2,4,6}
            int c1 = c + 1;
            int hi = s >> 10;
            int p0 = (c  & ~7) | ((c  & 3) << 1) | ((c  & 4) >> 2);
            int p1 = (c1 & ~7) | ((c1 & 3) << 1) | ((c1 & 4) >> 2);
            size_t r0 = ((size_t)b * S_ + h * 128 + d * 2 + hi) * D_;
            size_t r1 = ((size_t)b * S_ + h * 128 + (d + 8) * 2 + hi) * D_;
            out[r0 + p0] = round_tf32(acc[j][0]);
            out[r0 + p1] = round_tf32(acc[j][1]);
            out[r1 + p0] = round_tf32(acc[j][2]);
            out[r1 + p1] = round_tf32(acc[j][3]);
        }
    }
}

// ---------------------------------------------------------------------------
extern "C" void kernel_launch(void* const* d_in, const int* in_sizes, int n_in,
                              void* d_out, int out_size)
{
    const float* X  = (const float*)d_in[0];
    const float* W1 = (const float*)d_in[1];
    const float* b1 = (const float*)d_in[2];
    const float* W2 = (const float*)d_in[3];
    const float* b2 = (const float*)d_in[4];
    float* out = (float*)d_out;

    float *qkv, *att, *Xr, *W1r, *W2r, *wp;
    cudaGetSymbolAddress((void**)&qkv, g_qkv);
    cudaGetSymbolAddress((void**)&att, g_att);
    cudaGetSymbolAddress((void**)&Xr,  g_Xr);
    cudaGetSymbolAddress((void**)&W1r, g_W1r);
    cudaGetSymbolAddress((void**)&W2r, g_W2r);
    cudaGetSymbolAddress((void**)&wp,  g_wp);

    cudaFuncSetAttribute(gemm_mma, cudaFuncAttributeMaxDynamicSharedMemorySize, GEMM_SMEM);

    // 0) pre-round + K-permute inputs
    round_inputs<<<(TOT8 + 255) / 256, 256>>>(
        (const float4*)X, (const float4*)W1, (const float4*)W2,
        (float4*)Xr, (float4*)W1r, (float4*)W2r);

    // 1) GEMM1: QKV = Xr @ W1r^T + b1   [8192, 3072]
    dim3 g1(3 * D_ / TN, (B_ * S_) / TM);
    gemm_mma<<<g1, 256, GEMM_SMEM>>>(Xr, W1r, b1, qkv, B_ * S_, 3 * D_, D_);

    // 2) attention (tensor-core)
    attn_scores<<<dim3(B_ * H_, NSPLIT), 256>>>(qkv, wp);
    attn_out<<<dim3(B_ * H_, NSPLIT), 256>>>(qkv, wp, att);

    // 3) GEMM3: out = att @ W2r^T + b2  [8192, 1024]
    dim3 g3(D_ / TN, (B_ * S_) / TM);
    gemm_mma<<<g3, 256, GEMM_SMEM>>>(att, W2r, b2, out, B_ * S_, D_, D_);
}

// round 13
// speedup vs baseline: 1.3819x; 1.1636x over previous
#include <cuda_runtime.h>
#include <cstdint>

#define B_  4
#define S_  2048
#define D_  1024
#define H_  16
#define DH_ 64
#define NSPLIT 8

// scratch
__device__ float g_qkv[(size_t)B_ * S_ * 3 * D_];   // [B*S, 3D]
__device__ float g_att[(size_t)B_ * S_ * D_];       // [B*S, D] scrambled, tf32-rounded
__device__ float g_Xr[(size_t)B_ * S_ * D_];        // tf32-rounded X
__device__ float g_W1r[(size_t)3 * D_ * D_];        // tf32-rounded W1
__device__ float g_W2r[(size_t)D_ * D_];            // tf32-rounded W2
__device__ float g_wp[(size_t)B_ * H_ * NSPLIT * 64 * 64]; // partial score tiles

// ---------------------------------------------------------------------------
__device__ __forceinline__ uint32_t s2u(const void* p) {
    return (uint32_t)__cvta_generic_to_shared(p);
}
__device__ __forceinline__ void cp16(uint32_t dst, const void* src) {
    asm volatile("cp.async.cg.shared.global [%0], [%1], 16;\n" :: "r"(dst), "l"(src));
}
__device__ __forceinline__ void cp_commit() {
    asm volatile("cp.async.commit_group;\n" ::: "memory");
}
__device__ __forceinline__ void cp_wait2() {
    asm volatile("cp.async.wait_group 2;\n" ::: "memory");
}
__device__ __forceinline__ float round_tf32(float v) {
    uint32_t r;
    asm("cvt.rna.tf32.f32 %0, %1;\n" : "=r"(r) : "f"(v));
    return __uint_as_float(r);
}
__device__ __forceinline__ void mma_tf32(
    float& c0, float& c1, float& c2, float& c3,
    float a0, float a1, float a2, float a3,
    float b0, float b1)
{
    asm volatile(
        "mma.sync.aligned.m16n8k8.row.col.f32.tf32.tf32.f32 "
        "{%0,%1,%2,%3}, {%4,%5,%6,%7}, {%8,%9}, {%0,%1,%2,%3};\n"
        : "+f"(c0), "+f"(c1), "+f"(c2), "+f"(c3)
        : "r"(__float_as_uint(a0)), "r"(__float_as_uint(a1)),
          "r"(__float_as_uint(a2)), "r"(__float_as_uint(a3)),
          "r"(__float_as_uint(b0)), "r"(__float_as_uint(b1)));
}

// ---------------------------------------------------------------------------
// Pre-round inputs to tf32 (rna)
// ---------------------------------------------------------------------------
#define NX   (B_ * S_ * D_ / 4)
#define NW1  (3 * D_ * D_ / 4)
#define NW2  (D_ * D_ / 4)

__global__ void __launch_bounds__(256) round_inputs(
    const float4* __restrict__ X, const float4* __restrict__ W1,
    const float4* __restrict__ W2, float4* __restrict__ Xr,
    float4* __restrict__ W1r, float4* __restrict__ W2r)
{
    int i = blockIdx.x * blockDim.x + threadIdx.x;
    const float4* src; float4* dst; int idx;
    if (i < NX)            { src = X;  dst = Xr;  idx = i; }
    else if (i < NX + NW1) { src = W1; dst = W1r; idx = i - NX; }
    else if (i < NX + NW1 + NW2) { src = W2; dst = W2r; idx = i - NX - NW1; }
    else return;
    float4 v = src[idx];
    v.x = round_tf32(v.x); v.y = round_tf32(v.y);
    v.z = round_tf32(v.z); v.w = round_tf32(v.w);
    dst[idx] = v;
}

// ---------------------------------------------------------------------------
// tf32 mma.sync GEMM (NT): C = A @ W^T + bias. Inputs pre-rounded.
// CTA 128x256, warp 64x64, BK=32, 4-stage cp.async (loads issued before MMA).
// ---------------------------------------------------------------------------
#define TM 128
#define TN 256
#define TK 32
#define NSTAGE 4
#define A_FLOATS (128 * 32)
#define B_FLOATS (256 * 32)
#define GEMM_SMEM (NSTAGE * (A_FLOATS + B_FLOATS) * 4)   // 192 KB

__global__ void __launch_bounds__(256, 1) gemm_mma(
    const float* __restrict__ A, const float* __restrict__ W,
    const float* __restrict__ bias, float* __restrict__ C,
    int M, int N, int K)
{
    extern __shared__ float smem[];
    float* As = smem;                           // [NSTAGE][4096]
    float* Bs = smem + NSTAGE * A_FLOATS;       // [NSTAGE][8192]
    const uint32_t sA0 = s2u(As);
    const uint32_t sB0 = s2u(Bs);

    const int tid = threadIdx.x;
    const int wid = tid >> 5;
    const int lid = tid & 31;
    const int wm  = wid & 1;          // 2 warp rows -> 64 M
    const int wn  = wid >> 1;         // 4 warp cols -> 64 N
    const int g   = lid >> 2;
    const int t   = lid & 3;
    const int bm  = blockIdx.y * TM;
    const int bn  = blockIdx.x * TN;

    const int lrow = tid >> 3;        // 0..31
    const int lc4  = tid & 7;
    const uint32_t ldst = ((uint32_t)(lc4 ^ (lrow & 7))) * 16;

    float acc[4][8][4];
#pragma unroll
    for (int i = 0; i < 4; i++)
#pragma unroll
        for (int j = 0; j < 8; j++)
#pragma unroll
            for (int q = 0; q < 4; q++) acc[i][j][q] = 0.f;

    const int NCHUNK = K / TK;

#pragma unroll
    for (int p = 0; p < NSTAGE - 1; p++) {
        const float* Ag = A + (size_t)(bm + lrow) * K + p * TK + lc4 * 4;
        const float* Wg = W + (size_t)(bn + lrow) * K + p * TK + lc4 * 4;
        uint32_t dA = sA0 + p * (A_FLOATS * 4) + lrow * 128 + ldst;
        uint32_t dB = sB0 + p * (B_FLOATS * 4) + lrow * 128 + ldst;
#pragma unroll
        for (int r = 0; r < 4; r++)
            cp16(dA + r * (32 * 128), Ag + (size_t)(r * 32) * K);
#pragma unroll
        for (int r = 0; r < 8; r++)
            cp16(dB + r * (32 * 128), Wg + (size_t)(r * 32) * K);
        cp_commit();
    }

    const int swz = g << 2;

    for (int kc = 0; kc < NCHUNK; kc++) {
        cp_wait2();                 // group kc complete (kc+1, kc+2 may fly)
        __syncthreads();

        // issue loads for stage kc+NSTAGE-1 FIRST (buffer free: last read at kc-1)
        const int nk = kc + NSTAGE - 1;
        if (nk < NCHUNK) {
            const int sn = nk % NSTAGE;
            const float* Ag = A + (size_t)(bm + lrow) * K + nk * TK + lc4 * 4;
            const float* Wg = W + (size_t)(bn + lrow) * K + nk * TK + lc4 * 4;
            uint32_t dA = sA0 + sn * (A_FLOATS * 4) + lrow * 128 + ldst;
            uint32_t dB = sB0 + sn * (B_FLOATS * 4) + lrow * 128 + ldst;
#pragma unroll
            for (int r = 0; r < 4; r++)
                cp16(dA + r * (32 * 128), Ag + (size_t)(r * 32) * K);
#pragma unroll
            for (int r = 0; r < 8; r++)
                cp16(dB + r * (32 * 128), Wg + (size_t)(r * 32) * K);
        }
        cp_commit();

        const int s = kc % NSTAGE;
        const uint32_t* as = (const uint32_t*)(As + s * A_FLOATS + (wm * 64 + g) * 32);
        const uint32_t* bs = (const uint32_t*)(Bs + s * B_FLOATS + (wn * 64 + g) * 32);

#pragma unroll
        for (int kk = 0; kk < 4; kk++) {
            const int k0 = kk * 8;
            const int ck0 = (k0 + t) ^ swz;
            const int ck1 = (k0 + t + 4) ^ swz;

            uint32_t af[4][4];
#pragma unroll
            for (int i = 0; i < 4; i++) {
                const uint32_t* ai = as + i * (16 * 32);
                af[i][0] = ai[ck0];
                af[i][1] = ai[8 * 32 + ck0];
                af[i][2] = ai[ck1];
                af[i][3] = ai[8 * 32 + ck1];
            }
            uint32_t bf[8][2];
#pragma unroll
            for (int j = 0; j < 8; j++) {
                const uint32_t* bj = bs + j * (8 * 32);
                bf[j][0] = bj[ck0];
                bf[j][1] = bj[ck1];
            }
#pragma unroll
            for (int i = 0; i < 4; i++)
#pragma unroll
                for (int j = 0; j < 8; j++)
                    mma_tf32(acc[i][j][0], acc[i][j][1], acc[i][j][2], acc[i][j][3],
                             __uint_as_float(af[i][0]), __uint_as_float(af[i][1]),
                             __uint_as_float(af[i][2]), __uint_as_float(af[i][3]),
                             __uint_as_float(bf[j][0]), __uint_as_float(bf[j][1]));
        }
    }

    // epilogue
#pragma unroll
    for (int i = 0; i < 4; i++) {
        const int row0 = bm + wm * 64 + i * 16 + g;
#pragma unroll
        for (int j = 0; j < 8; j++) {
            const int col = bn + wn * 64 + j * 8 + 2 * t;
            const float b0 = bias[col];
            const float b1 = bias[col + 1];
            float2 v0 = make_float2(acc[i][j][0] + b0, acc[i][j][1] + b1);
            float2 v1 = make_float2(acc[i][j][2] + b0, acc[i][j][3] + b1);
            *(float2*)&C[(size_t)row0 * N + col] = v0;
            *(float2*)&C[(size_t)(row0 + 8) * N + col] = v1;
        }
    }
}

// ---------------------------------------------------------------------------
// Attention stage A (tensor): partial scores. grid (64, NSPLIT).
// ---------------------------------------------------------------------------
#define PAD 68

__global__ void __launch_bounds__(256) attn_scores(
    const float* __restrict__ qkv, float* __restrict__ wp)
{
    __shared__ float sm[2 * 64 * PAD];
    float* S0 = sm;                 // Q chunk [s][d], tf32-rounded
    float* S1 = sm + 64 * PAD;      // K chunk [s][e], tf32-rounded

    const int bh = blockIdx.x;
    const int split = blockIdx.y;
    const int b  = bh >> 4;
    const int h  = bh & 15;
    const float* base = qkv + (size_t)b * S_ * (3 * D_);

    const int tid = threadIdx.x;
    const int wid = tid >> 5;
    const int lid = tid & 31;
    const int g   = lid >> 2;
    const int t   = lid & 3;
    const int wm  = wid & 3;        // 4 m-blocks of 16 -> 64 d
    const int wn  = wid >> 2;       // 2 n-blocks of 32 -> 64 e
    const int dA  = wm * 16 + g;
    const int nB  = wn * 32 + g;

    float acc[4][4];
#pragma unroll
    for (int j = 0; j < 4; j++)
#pragma unroll
        for (int q = 0; q < 4; q++) acc[j][q] = 0.f;

    const int sbeg = split * (S_ / NSPLIT);
    for (int s0 = sbeg; s0 < sbeg + S_ / NSPLIT; s0 += 64) {
#pragma unroll
        for (int jj = 0; jj < 4; jj++) {
            int l  = tid + jj * 256;
            int ss = l >> 4;
            int c4 = (l & 15) * 4;
            const float* gp = base + (size_t)(s0 + ss) * (3 * D_) + h * DH_ + c4;
            float4 q = *(const float4*)gp;
            float4 k = *(const float4*)(gp + D_);
            q.x = round_tf32(q.x); q.y = round_tf32(q.y);
            q.z = round_tf32(q.z); q.w = round_tf32(q.w);
            k.x = round_tf32(k.x); k.y = round_tf32(k.y);
            k.z = round_tf32(k.z); k.w = round_tf32(k.w);
            *(float4*)&S0[ss * PAD + c4] = q;
            *(float4*)&S1[ss * PAD + c4] = k;
        }
        __syncthreads();

#pragma unroll
        for (int ko = 0; ko < 8; ko++) {
            const int kr = ko * 8 + t;          // s index (contraction)
            float a0 = S0[kr * PAD + dA];
            float a1 = S0[kr * PAD + dA + 8];
            float a2 = S0[(kr + 4) * PAD + dA];
            float a3 = S0[(kr + 4) * PAD + dA + 8];
#pragma unroll
            for (int j = 0; j < 4; j++) {
                float b0 = S1[kr * PAD + nB + j * 8];
                float b1 = S1[(kr + 4) * PAD + nB + j * 8];
                mma_tf32(acc[j][0], acc[j][1], acc[j][2], acc[j][3],
                         a0, a1, a2, a3, b0, b1);
            }
        }
        __syncthreads();
    }

    float* wt = wp + ((size_t)(bh * NSPLIT + split)) * 4096;
    const int col0 = wn * 32 + 2 * t;
#pragma unroll
    for (int j = 0; j < 4; j++) {
        *(float2*)&wt[dA * 64 + col0 + j * 8]       = make_float2(acc[j][0], acc[j][1]);
        *(float2*)&wt[(dA + 8) * 64 + col0 + j * 8] = make_float2(acc[j][2], acc[j][3]);
    }
}

// ---------------------------------------------------------------------------
// Attention stage B (tensor): reduce partials + softmax + o = w @ V,
// scrambled tf32-rounded store. grid (64, NSPLIT).
// ---------------------------------------------------------------------------
__global__ void __launch_bounds__(256) attn_out(
    const float* __restrict__ qkv, const float* __restrict__ wp,
    float* __restrict__ out)
{
    __shared__ float sm[2 * 64 * PAD];
    float* S0 = sm;                 // w
    float* S1 = sm + 64 * PAD;      // V stage

    const int bh = blockIdx.x;
    const int split = blockIdx.y;
    const int b  = bh >> 4;
    const int h  = bh & 15;
    const float* base = qkv + (size_t)b * S_ * (3 * D_);
    const float* wt = wp + (size_t)bh * NSPLIT * 4096;

    const int tid = threadIdx.x;
    const int wid = tid >> 5;
    const int lid = tid & 31;
    const int g   = lid >> 2;
    const int t   = lid & 3;
    const int wm  = wid & 3;        // 4 m-blocks of 16 -> 64 d
    const int wn  = wid >> 2;       // 2 n-blocks of 32 -> 64 s per chunk
    const float scale = rsqrtf((float)S_);

    // reduce NSPLIT partials into S0 (w), scaled
    for (int l = tid; l < 1024; l += 256) {
        int d  = l >> 4;
        int e4 = (l & 15) * 4;
        float4 r = make_float4(0.f, 0.f, 0.f, 0.f);
#pragma unroll
        for (int p = 0; p < NSPLIT; p++) {
            float4 q = *(const float4*)&wt[(size_t)p * 4096 + d * 64 + e4];
            r.x += q.x; r.y += q.y; r.z += q.z; r.w += q.w;
        }
        r.x *= scale; r.y *= scale; r.z *= scale; r.w *= scale;
        *(float4*)&S0[d * PAD + e4] = r;
    }
    __syncthreads();

    // softmax rows (fp32), round result to tf32 in place
    if (tid < 64) {
        float* row = &S0[tid * PAD];
        float m = -1e30f;
#pragma unroll
        for (int e = 0; e < 64; e++) m = fmaxf(m, row[e]);
        float s = 0.f;
#pragma unroll
        for (int e = 0; e < 64; e++) { float v = expf(row[e] - m); row[e] = v; s += v; }
        float inv = 1.f / s;
#pragma unroll
        for (int e = 0; e < 64; e++) row[e] = round_tf32(row[e] * inv);
    }
    __syncthreads();

    // hoist w fragments (constant across chunks): 32 regs
    float aw[8][4];
#pragma unroll
    for (int ko = 0; ko < 8; ko++) {
        const int kr = ko * 8 + t;              // e index (contraction)
        aw[ko][0] = S0[(wm * 16 + g) * PAD + kr];
        aw[ko][1] = S0[(wm * 16 + g + 8) * PAD + kr];
        aw[ko][2] = S0[(wm * 16 + g) * PAD + kr + 4];
        aw[ko][3] = S0[(wm * 16 + g + 8) * PAD + kr + 4];
    }

    const int sbeg = split * (S_ / NSPLIT);
    const int d  = wm * 16 + g;
    const int sl = wn * 32 + 2 * t;

    for (int s0 = sbeg; s0 < sbeg + S_ / NSPLIT; s0 += 64) {
#pragma unroll
        for (int jj = 0; jj < 4; jj++) {
            int l  = tid + jj * 256;
            int ss = l >> 4;
            int e4 = (l & 15) * 4;
            float4 v = *(const float4*)(base + (size_t)(s0 + ss) * (3 * D_) + 2 * D_ + h * DH_ + e4);
            v.x = round_tf32(v.x); v.y = round_tf32(v.y);
            v.z = round_tf32(v.z); v.w = round_tf32(v.w);
            *(float4*)&S1[ss * PAD + e4] = v;
        }
        __syncthreads();

        float acc[4][4];
#pragma unroll
        for (int j = 0; j < 4; j++)
#pragma unroll
            for (int q = 0; q < 4; q++) acc[j][q] = 0.f;

#pragma unroll
        for (int ko = 0; ko < 8; ko++) {
            const int kr = ko * 8 + t;
#pragma unroll
            for (int j = 0; j < 4; j++) {
                const float* vr = &S1[(wn * 32 + j * 8 + g) * PAD];
                float b0 = vr[kr];
                float b1 = vr[kr + 4];
                mma_tf32(acc[j][0], acc[j][1], acc[j][2], acc[j][3],
                         aw[ko][0], aw[ko][1], aw[ko][2], aw[ko][3], b0, b1);
            }
        }
        __syncthreads();

        // scrambled store: out[b][h*128 + 2d + (s>>10)][s & 1023]
#pragma unroll
        for (int j = 0; j < 4; j++) {
            int s = s0 + sl + j * 8;
            int col = s & 1023;
            int hi  = s >> 10;
            size_t r0 = ((size_t)b * S_ + h * 128 + d * 2 + hi) * D_ + col;
            size_t r1 = ((size_t)b * S_ + h * 128 + (d + 8) * 2 + hi) * D_ + col;
            *(float2*)&out[r0] = make_float2(round_tf32(acc[j][0]), round_tf32(acc[j][1]));
            *(float2*)&out[r1] = make_float2(round_tf32(acc[j][2]), round_tf32(acc[j][3]));
        }
    }
}

// ---------------------------------------------------------------------------
extern "C" void kernel_launch(void* const* d_in, const int* in_sizes, int n_in,
                              void* d_out, int out_size)
{
    const float* X  = (const float*)d_in[0];
    const float* W1 = (const float*)d_in[1];
    const float* b1 = (const float*)d_in[2];
    const float* W2 = (const float*)d_in[3];
    const float* b2 = (const float*)d_in[4];
    float* out = (float*)d_out;

    float *qkv, *att, *Xr, *W1r, *W2r, *wp;
    cudaGetSymbolAddress((void**)&qkv, g_qkv);
    cudaGetSymbolAddress((void**)&att, g_att);
    cudaGetSymbolAddress((void**)&Xr,  g_Xr);
    cudaGetSymbolAddress((void**)&W1r, g_W1r);
    cudaGetSymbolAddress((void**)&W2r, g_W2r);
    cudaGetSymbolAddress((void**)&wp,  g_wp);

    cudaFuncSetAttribute(gemm_mma, cudaFuncAttributeMaxDynamicSharedMemorySize, GEMM_SMEM);

    // 0) pre-round inputs to tf32
    int total4 = NX + NW1 + NW2;
    round_inputs<<<(total4 + 255) / 256, 256>>>(
        (const float4*)X, (const float4*)W1, (const float4*)W2,
        (float4*)Xr, (float4*)W1r, (float4*)W2r);

    // 1) GEMM1: QKV = Xr @ W1r^T + b1   [8192, 3072]
    dim3 g1(3 * D_ / TN, (B_ * S_) / TM);
    gemm_mma<<<g1, 256, GEMM_SMEM>>>(Xr, W1r, b1, qkv, B_ * S_, 3 * D_, D_);

    // 2) attention (tensor-core)
    attn_scores<<<dim3(B_ * H_, NSPLIT), 256>>>(qkv, wp);
    attn_out<<<dim3(B_ * H_, NSPLIT), 256>>>(qkv, wp, att);

    // 3) GEMM3: out = att @ W2r^T + b2  [8192, 1024]
    dim3 g3(D_ / TN, (B_ * S_) / TM);
    gemm_mma<<<g3, 256, GEMM_SMEM>>>(att, W2r, b2, out, B_ * S_, D_, D_);
}

// round 14
// speedup vs baseline: 1.3932x; 1.0081x over previous
#include <cuda_runtime.h>
#include <cstdint>

#define B_  4
#define S_  2048
#define D_  1024
#define H_  16
#define DH_ 64
#define NSPLIT 16

// scratch
__device__ float g_qkv[(size_t)B_ * S_ * 3 * D_];   // [B*S, 3D], tf32-rounded
__device__ float g_att[(size_t)B_ * S_ * D_];       // [B*S, D] scrambled, tf32-rounded
__device__ float g_Xr[(size_t)B_ * S_ * D_];        // tf32-rounded X
__device__ float g_W1r[(size_t)3 * D_ * D_];        // tf32-rounded W1
__device__ float g_W2r[(size_t)D_ * D_];            // tf32-rounded W2
__device__ float g_wp[(size_t)B_ * H_ * NSPLIT * 64 * 64]; // partial score tiles
__device__ float g_wf[(size_t)B_ * H_ * 64 * 64];   // final softmaxed w (tf32)

// ---------------------------------------------------------------------------
__device__ __forceinline__ uint32_t s2u(const void* p) {
    return (uint32_t)__cvta_generic_to_shared(p);
}
__device__ __forceinline__ void cp16(uint32_t dst, const void* src) {
    asm volatile("cp.async.cg.shared.global [%0], [%1], 16;\n" :: "r"(dst), "l"(src));
}
__device__ __forceinline__ void cp_commit() {
    asm volatile("cp.async.commit_group;\n" ::: "memory");
}
__device__ __forceinline__ void cp_wait1() {
    asm volatile("cp.async.wait_group 1;\n" ::: "memory");
}
__device__ __forceinline__ float round_tf32(float v) {
    uint32_t r;
    asm("cvt.rna.tf32.f32 %0, %1;\n" : "=r"(r) : "f"(v));
    return __uint_as_float(r);
}
__device__ __forceinline__ void mma_tf32(
    float& c0, float& c1, float& c2, float& c3,
    float a0, float a1, float a2, float a3,
    float b0, float b1)
{
    asm volatile(
        "mma.sync.aligned.m16n8k8.row.col.f32.tf32.tf32.f32 "
        "{%0,%1,%2,%3}, {%4,%5,%6,%7}, {%8,%9}, {%0,%1,%2,%3};\n"
        : "+f"(c0), "+f"(c1), "+f"(c2), "+f"(c3)
        : "r"(__float_as_uint(a0)), "r"(__float_as_uint(a1)),
          "r"(__float_as_uint(a2)), "r"(__float_as_uint(a3)),
          "r"(__float_as_uint(b0)), "r"(__float_as_uint(b1)));
}

// ---------------------------------------------------------------------------
// Pre-round inputs to tf32 (rna)
// ---------------------------------------------------------------------------
#define NX   (B_ * S_ * D_ / 4)
#define NW1  (3 * D_ * D_ / 4)
#define NW2  (D_ * D_ / 4)

__global__ void __launch_bounds__(256) round_inputs(
    const float4* __restrict__ X, const float4* __restrict__ W1,
    const float4* __restrict__ W2, float4* __restrict__ Xr,
    float4* __restrict__ W1r, float4* __restrict__ W2r)
{
    int i = blockIdx.x * blockDim.x + threadIdx.x;
    const float4* src; float4* dst; int idx;
    if (i < NX)            { src = X;  dst = Xr;  idx = i; }
    else if (i < NX + NW1) { src = W1; dst = W1r; idx = i - NX; }
    else if (i < NX + NW1 + NW2) { src = W2; dst = W2r; idx = i - NX - NW1; }
    else return;
    float4 v = src[idx];
    v.x = round_tf32(v.x); v.y = round_tf32(v.y);
    v.z = round_tf32(v.z); v.w = round_tf32(v.w);
    dst[idx] = v;
}

// ---------------------------------------------------------------------------
// tf32 mma.sync GEMM (NT): C = A @ W^T + bias. Inputs pre-rounded.
// CTA 128x256, warp 64x64, BK=32, 3-stage cp.async (R7 proven config).
// round_out != 0: round result to tf32 (feeds attention).
// ---------------------------------------------------------------------------
#define TM 128
#define TN 256
#define TK 32
#define NSTAGE 3
#define A_FLOATS (128 * 32)
#define B_FLOATS (256 * 32)
#define GEMM_SMEM (NSTAGE * (A_FLOATS + B_FLOATS) * 4)   // 144 KB

__global__ void __launch_bounds__(256, 1) gemm_mma(
    const float* __restrict__ A, const float* __restrict__ W,
    const float* __restrict__ bias, float* __restrict__ C,
    int M, int N, int K, int round_out)
{
    extern __shared__ float smem[];
    float* As = smem;                           // [NSTAGE][4096]
    float* Bs = smem + NSTAGE * A_FLOATS;       // [NSTAGE][8192]
    const uint32_t sA0 = s2u(As);
    const uint32_t sB0 = s2u(Bs);

    const int tid = threadIdx.x;
    const int wid = tid >> 5;
    const int lid = tid & 31;
    const int wm  = wid & 1;          // 2 warp rows -> 64 M
    const int wn  = wid >> 1;         // 4 warp cols -> 64 N
    const int g   = lid >> 2;
    const int t   = lid & 3;
    const int bm  = blockIdx.y * TM;
    const int bn  = blockIdx.x * TN;

    const int lrow = tid >> 3;        // 0..31
    const int lc4  = tid & 7;
    const uint32_t ldst = ((uint32_t)(lc4 ^ (lrow & 7))) * 16;

    float acc[4][8][4];
#pragma unroll
    for (int i = 0; i < 4; i++)
#pragma unroll
        for (int j = 0; j < 8; j++)
#pragma unroll
            for (int q = 0; q < 4; q++) acc[i][j][q] = 0.f;

    const int NCHUNK = K / TK;

#pragma unroll
    for (int p = 0; p < NSTAGE - 1; p++) {
        const float* Ag = A + (size_t)(bm + lrow) * K + p * TK + lc4 * 4;
        const float* Wg = W + (size_t)(bn + lrow) * K + p * TK + lc4 * 4;
        uint32_t dA = sA0 + p * (A_FLOATS * 4) + lrow * 128 + ldst;
        uint32_t dB = sB0 + p * (B_FLOATS * 4) + lrow * 128 + ldst;
#pragma unroll
        for (int r = 0; r < 4; r++)
            cp16(dA + r * (32 * 128), Ag + (size_t)(r * 32) * K);
#pragma unroll
        for (int r = 0; r < 8; r++)
            cp16(dB + r * (32 * 128), Wg + (size_t)(r * 32) * K);
        cp_commit();
    }

    const int swz = g << 2;

    for (int kc = 0; kc < NCHUNK; kc++) {
        cp_wait1();
        __syncthreads();

        const int s = kc % NSTAGE;
        const uint32_t* as = (const uint32_t*)(As + s * A_FLOATS + (wm * 64 + g) * 32);
        const uint32_t* bs = (const uint32_t*)(Bs + s * B_FLOATS + (wn * 64 + g) * 32);

#pragma unroll
        for (int kk = 0; kk < 4; kk++) {
            const int k0 = kk * 8;
            const int ck0 = (k0 + t) ^ swz;
            const int ck1 = (k0 + t + 4) ^ swz;

            uint32_t af[4][4];
#pragma unroll
            for (int i = 0; i < 4; i++) {
                const uint32_t* ai = as + i * (16 * 32);
                af[i][0] = ai[ck0];
                af[i][1] = ai[8 * 32 + ck0];
                af[i][2] = ai[ck1];
                af[i][3] = ai[8 * 32 + ck1];
            }
            uint32_t bf[8][2];
#pragma unroll
            for (int j = 0; j < 8; j++) {
                const uint32_t* bj = bs + j * (8 * 32);
                bf[j][0] = bj[ck0];
                bf[j][1] = bj[ck1];
            }
#pragma unroll
            for (int i = 0; i < 4; i++)
#pragma unroll
                for (int j = 0; j < 8; j++)
                    mma_tf32(acc[i][j][0], acc[i][j][1], acc[i][j][2], acc[i][j][3],
                             __uint_as_float(af[i][0]), __uint_as_float(af[i][1]),
                             __uint_as_float(af[i][2]), __uint_as_float(af[i][3]),
                             __uint_as_float(bf[j][0]), __uint_as_float(bf[j][1]));
        }

        const int nk = kc + NSTAGE - 1;
        if (nk < NCHUNK) {
            const int sn = nk % NSTAGE;
            const float* Ag = A + (size_t)(bm + lrow) * K + nk * TK + lc4 * 4;
            const float* Wg = W + (size_t)(bn + lrow) * K + nk * TK + lc4 * 4;
            uint32_t dA = sA0 + sn * (A_FLOATS * 4) + lrow * 128 + ldst;
            uint32_t dB = sB0 + sn * (B_FLOATS * 4) + lrow * 128 + ldst;
#pragma unroll
            for (int r = 0; r < 4; r++)
                cp16(dA + r * (32 * 128), Ag + (size_t)(r * 32) * K);
#pragma unroll
            for (int r = 0; r < 8; r++)
                cp16(dB + r * (32 * 128), Wg + (size_t)(r * 32) * K);
        }
        cp_commit();
    }

    // epilogue
#pragma unroll
    for (int i = 0; i < 4; i++) {
        const int row0 = bm + wm * 64 + i * 16 + g;
#pragma unroll
        for (int j = 0; j < 8; j++) {
            const int col = bn + wn * 64 + j * 8 + 2 * t;
            const float b0 = bias[col];
            const float b1 = bias[col + 1];
            float2 v0 = make_float2(acc[i][j][0] + b0, acc[i][j][1] + b1);
            float2 v1 = make_float2(acc[i][j][2] + b0, acc[i][j][3] + b1);
            if (round_out) {
                v0.x = round_tf32(v0.x); v0.y = round_tf32(v0.y);
                v1.x = round_tf32(v1.x); v1.y = round_tf32(v1.y);
            }
            *(float2*)&C[(size_t)row0 * N + col] = v0;
            *(float2*)&C[(size_t)(row0 + 8) * N + col] = v1;
        }
    }
}

// ---------------------------------------------------------------------------
// Attention stage A (tensor): partial scores. grid (64, NSPLIT).
// qkv already tf32-rounded -> staging is a pure copy.
// ---------------------------------------------------------------------------
#define PAD 68

__global__ void __launch_bounds__(256) attn_scores(
    const float* __restrict__ qkv, float* __restrict__ wp)
{
    __shared__ float sm[2 * 64 * PAD];
    float* S0 = sm;                 // Q chunk [s][d]
    float* S1 = sm + 64 * PAD;      // K chunk [s][e]

    const int bh = blockIdx.x;
    const int split = blockIdx.y;
    const int b  = bh >> 4;
    const int h  = bh & 15;
    const float* base = qkv + (size_t)b * S_ * (3 * D_);

    const int tid = threadIdx.x;
    const int wid = tid >> 5;
    const int lid = tid & 31;
    const int g   = lid >> 2;
    const int t   = lid & 3;
    const int wm  = wid & 3;        // 4 m-blocks of 16 -> 64 d
    const int wn  = wid >> 2;       // 2 n-blocks of 32 -> 64 e
    const int dA  = wm * 16 + g;
    const int nB  = wn * 32 + g;

    float acc[4][4];
#pragma unroll
    for (int j = 0; j < 4; j++)
#pragma unroll
        for (int q = 0; q < 4; q++) acc[j][q] = 0.f;

    const int sbeg = split * (S_ / NSPLIT);
    for (int s0 = sbeg; s0 < sbeg + S_ / NSPLIT; s0 += 64) {
#pragma unroll
        for (int jj = 0; jj < 4; jj++) {
            int l  = tid + jj * 256;
            int ss = l >> 4;
            int c4 = (l & 15) * 4;
            const float* gp = base + (size_t)(s0 + ss) * (3 * D_) + h * DH_ + c4;
            *(float4*)&S0[ss * PAD + c4] = *(const float4*)gp;
            *(float4*)&S1[ss * PAD + c4] = *(const float4*)(gp + D_);
        }
        __syncthreads();

#pragma unroll
        for (int ko = 0; ko < 8; ko++) {
            const int kr = ko * 8 + t;          // s index (contraction)
            float a0 = S0[kr * PAD + dA];
            float a1 = S0[kr * PAD + dA + 8];
            float a2 = S0[(kr + 4) * PAD + dA];
            float a3 = S0[(kr + 4) * PAD + dA + 8];
#pragma unroll
            for (int j = 0; j < 4; j++) {
                float b0 = S1[kr * PAD + nB + j * 8];
                float b1 = S1[(kr + 4) * PAD + nB + j * 8];
                mma_tf32(acc[j][0], acc[j][1], acc[j][2], acc[j][3],
                         a0, a1, a2, a3, b0, b1);
            }
        }
        __syncthreads();
    }

    float* wt = wp + ((size_t)(bh * NSPLIT + split)) * 4096;
    const int col0 = wn * 32 + 2 * t;
#pragma unroll
    for (int j = 0; j < 4; j++) {
        *(float2*)&wt[dA * 64 + col0 + j * 8]       = make_float2(acc[j][0], acc[j][1]);
        *(float2*)&wt[(dA + 8) * 64 + col0 + j * 8] = make_float2(acc[j][2], acc[j][3]);
    }
}

// ---------------------------------------------------------------------------
// Softmax kernel: reduce NSPLIT partials + softmax + tf32 round.
// grid 64 (bh), block 64 (one thread per row d).
// ---------------------------------------------------------------------------
__global__ void __launch_bounds__(64) attn_softmax(
    const float* __restrict__ wp, float* __restrict__ wf)
{
    const int bh = blockIdx.x;
    const int d  = threadIdx.x;
    const float* wt = wp + (size_t)bh * NSPLIT * 4096;
    const float scale = rsqrtf((float)S_);

    float row[64];
#pragma unroll
    for (int e4 = 0; e4 < 16; e4++) {
        float4 r = make_float4(0.f, 0.f, 0.f, 0.f);
#pragma unroll
        for (int p = 0; p < NSPLIT; p++) {
            float4 q = *(const float4*)&wt[(size_t)p * 4096 + d * 64 + e4 * 4];
            r.x += q.x; r.y += q.y; r.z += q.z; r.w += q.w;
        }
        row[e4 * 4 + 0] = r.x * scale;
        row[e4 * 4 + 1] = r.y * scale;
        row[e4 * 4 + 2] = r.z * scale;
        row[e4 * 4 + 3] = r.w * scale;
    }
    float m = -1e30f;
#pragma unroll
    for (int e = 0; e < 64; e++) m = fmaxf(m, row[e]);
    float s = 0.f;
#pragma unroll
    for (int e = 0; e < 64; e++) { float v = expf(row[e] - m); row[e] = v; s += v; }
    float inv = 1.f / s;
    float* wo = wf + (size_t)bh * 4096 + d * 64;
#pragma unroll
    for (int e4 = 0; e4 < 16; e4++) {
        float4 v;
        v.x = round_tf32(row[e4 * 4 + 0] * inv);
        v.y = round_tf32(row[e4 * 4 + 1] * inv);
        v.z = round_tf32(row[e4 * 4 + 2] * inv);
        v.w = round_tf32(row[e4 * 4 + 3] * inv);
        *(float4*)&wo[e4 * 4] = v;
    }
}

// ---------------------------------------------------------------------------
// Attention stage B (tensor): o = w @ V, scrambled store (already-rounded
// inputs -> pure copies). grid (64, NSPLIT).
// ---------------------------------------------------------------------------
__global__ void __launch_bounds__(256) attn_out(
    const float* __restrict__ qkv, const float* __restrict__ wf,
    float* __restrict__ out)
{
    __shared__ float sm[2 * 64 * PAD];
    float* S0 = sm;                 // w (final)
    float* S1 = sm + 64 * PAD;      // V stage

    const int bh = blockIdx.x;
    const int split = blockIdx.y;
    const int b  = bh >> 4;
    const int h  = bh & 15;
    const float* base = qkv + (size_t)b * S_ * (3 * D_);

    const int tid = threadIdx.x;
    const int wid = tid >> 5;
    const int lid = tid & 31;
    const int g   = lid >> 2;
    const int t   = lid & 3;
    const int wm  = wid & 3;        // 4 m-blocks of 16 -> 64 d
    const int wn  = wid >> 2;       // 2 n-blocks of 32 -> 64 s per chunk

    // copy final w into smem (L2-hot, 16 KB)
    const float* wsrc = wf + (size_t)bh * 4096;
    for (int l = tid; l < 1024; l += 256) {
        int d  = l >> 4;
        int e4 = (l & 15) * 4;
        *(float4*)&S0[d * PAD + e4] = *(const float4*)&wsrc[d * 64 + e4];
    }
    __syncthreads();

    // hoist w fragments (constant across chunks): 32 regs
    float aw[8][4];
#pragma unroll
    for (int ko = 0; ko < 8; ko++) {
        const int kr = ko * 8 + t;              // e index (contraction)
        aw[ko][0] = S0[(wm * 16 + g) * PAD + kr];
        aw[ko][1] = S0[(wm * 16 + g + 8) * PAD + kr];
        aw[ko][2] = S0[(wm * 16 + g) * PAD + kr + 4];
        aw[ko][3] = S0[(wm * 16 + g + 8) * PAD + kr + 4];
    }

    const int sbeg = split * (S_ / NSPLIT);
    const int d  = wm * 16 + g;
    const int sl = wn * 32 + 2 * t;

    for (int s0 = sbeg; s0 < sbeg + S_ / NSPLIT; s0 += 64) {
#pragma unroll
        for (int jj = 0; jj < 4; jj++) {
            int l  = tid + jj * 256;
            int ss = l >> 4;
            int e4 = (l & 15) * 4;
            *(float4*)&S1[ss * PAD + e4] =
                *(const float4*)(base + (size_t)(s0 + ss) * (3 * D_) + 2 * D_ + h * DH_ + e4);
        }
        __syncthreads();

        float acc[4][4];
#pragma unroll
        for (int j = 0; j < 4; j++)
#pragma unroll
            for (int q = 0; q < 4; q++) acc[j][q] = 0.f;

#pragma unroll
        for (int ko = 0; ko < 8; ko++) {
            const int kr = ko * 8 + t;
#pragma unroll
            for (int j = 0; j < 4; j++) {
                const float* vr = &S1[(wn * 32 + j * 8 + g) * PAD];
                float b0 = vr[kr];
                float b1 = vr[kr + 4];
                mma_tf32(acc[j][0], acc[j][1], acc[j][2], acc[j][3],
                         aw[ko][0], aw[ko][1], aw[ko][2], aw[ko][3], b0, b1);
            }
        }
        __syncthreads();

        // scrambled store: out[b][h*128 + 2d + (s>>10)][s & 1023]
#pragma unroll
        for (int j = 0; j < 4; j++) {
            int s = s0 + sl + j * 8;
            int col = s & 1023;
            int hi  = s >> 10;
            size_t r0 = ((size_t)b * S_ + h * 128 + d * 2 + hi) * D_ + col;
            size_t r1 = ((size_t)b * S_ + h * 128 + (d + 8) * 2 + hi) * D_ + col;
            *(float2*)&out[r0] = make_float2(round_tf32(acc[j][0]), round_tf32(acc[j][1]));
            *(float2*)&out[r1] = make_float2(round_tf32(acc[j][2]), round_tf32(acc[j][3]));
        }
    }
}

// ---------------------------------------------------------------------------
extern "C" void kernel_launch(void* const* d_in, const int* in_sizes, int n_in,
                              void* d_out, int out_size)
{
    const float* X  = (const float*)d_in[0];
    const float* W1 = (const float*)d_in[1];
    const float* b1 = (const float*)d_in[2];
    const float* W2 = (const float*)d_in[3];
    const float* b2 = (const float*)d_in[4];
    float* out = (float*)d_out;

    float *qkv, *att, *Xr, *W1r, *W2r, *wp, *wf;
    cudaGetSymbolAddress((void**)&qkv, g_qkv);
    cudaGetSymbolAddress((void**)&att, g_att);
    cudaGetSymbolAddress((void**)&Xr,  g_Xr);
    cudaGetSymbolAddress((void**)&W1r, g_W1r);
    cudaGetSymbolAddress((void**)&W2r, g_W2r);
    cudaGetSymbolAddress((void**)&wp,  g_wp);
    cudaGetSymbolAddress((void**)&wf,  g_wf);

    cudaFuncSetAttribute(gemm_mma, cudaFuncAttributeMaxDynamicSharedMemorySize, GEMM_SMEM);

    // 0) pre-round inputs to tf32
    int total4 = NX + NW1 + NW2;
    round_inputs<<<(total4 + 255) / 256, 256>>>(
        (const float4*)X, (const float4*)W1, (const float4*)W2,
        (float4*)Xr, (float4*)W1r, (float4*)W2r);

    // 1) GEMM1: QKV = Xr @ W1r^T + b1, rounded to tf32   [8192, 3072]
    dim3 g1(3 * D_ / TN, (B_ * S_) / TM);
    gemm_mma<<<g1, 256, GEMM_SMEM>>>(Xr, W1r, b1, qkv, B_ * S_, 3 * D_, D_, 1);

    // 2) attention (tensor-core)
    attn_scores<<<dim3(B_ * H_, NSPLIT), 256>>>(qkv, wp);
    attn_softmax<<<B_ * H_, 64>>>(wp, wf);
    attn_out<<<dim3(B_ * H_, NSPLIT), 256>>>(qkv, wf, att);

    // 3) GEMM3: out = att @ W2r^T + b2  [8192, 1024]
    dim3 g3(D_ / TN, (B_ * S_) / TM);
    gemm_mma<<<g3, 256, GEMM_SMEM>>>(att, W2r, b2, out, B_ * S_, D_, D_, 0);
}

// round 15
// speedup vs baseline: 1.4205x; 1.0196x over previous
#include <cuda_runtime.h>
#include <cstdint>

#define B_  4
#define S_  2048
#define D_  1024
#define H_  16
#define DH_ 64
#define NSPLIT 8

// scratch
__device__ float g_qkv[(size_t)B_ * S_ * 3 * D_];   // [B*S, 3D], tf32-rounded
__device__ float g_att[(size_t)B_ * S_ * D_];       // [B*S, D] scrambled, tf32-rounded
__device__ float g_Xr[(size_t)B_ * S_ * D_];        // tf32-rounded X
__device__ float g_W1r[(size_t)3 * D_ * D_];        // tf32-rounded W1
__device__ float g_W2r[(size_t)D_ * D_];            // tf32-rounded W2
__device__ float g_wp[(size_t)B_ * H_ * NSPLIT * 64 * 64]; // partial score tiles
__device__ float g_wf[(size_t)B_ * H_ * 64 * 64];   // final softmaxed w (tf32)

// ---------------------------------------------------------------------------
__device__ __forceinline__ uint32_t s2u(const void* p) {
    return (uint32_t)__cvta_generic_to_shared(p);
}
__device__ __forceinline__ void cp16(uint32_t dst, const void* src) {
    asm volatile("cp.async.cg.shared.global [%0], [%1], 16;\n" :: "r"(dst), "l"(src));
}
__device__ __forceinline__ void cp_commit() {
    asm volatile("cp.async.commit_group;\n" ::: "memory");
}
__device__ __forceinline__ void cp_wait1() {
    asm volatile("cp.async.wait_group 1;\n" ::: "memory");
}
__device__ __forceinline__ float round_tf32(float v) {
    uint32_t r;
    asm("cvt.rna.tf32.f32 %0, %1;\n" : "=r"(r) : "f"(v));
    return __uint_as_float(r);
}
__device__ __forceinline__ void mma_tf32(
    float& c0, float& c1, float& c2, float& c3,
    float a0, float a1, float a2, float a3,
    float b0, float b1)
{
    asm volatile(
        "mma.sync.aligned.m16n8k8.row.col.f32.tf32.tf32.f32 "
        "{%0,%1,%2,%3}, {%4,%5,%6,%7}, {%8,%9}, {%0,%1,%2,%3};\n"
        : "+f"(c0), "+f"(c1), "+f"(c2), "+f"(c3)
        : "r"(__float_as_uint(a0)), "r"(__float_as_uint(a1)),
          "r"(__float_as_uint(a2)), "r"(__float_as_uint(a3)),
          "r"(__float_as_uint(b0)), "r"(__float_as_uint(b1)));
}

// ---------------------------------------------------------------------------
// Pre-round inputs to tf32 (rna)
// ---------------------------------------------------------------------------
#define NX   (B_ * S_ * D_ / 4)
#define NW1  (3 * D_ * D_ / 4)
#define NW2  (D_ * D_ / 4)

__global__ void __launch_bounds__(256) round_inputs(
    const float4* __restrict__ X, const float4* __restrict__ W1,
    const float4* __restrict__ W2, float4* __restrict__ Xr,
    float4* __restrict__ W1r, float4* __restrict__ W2r)
{
    int i = blockIdx.x * blockDim.x + threadIdx.x;
    const float4* src; float4* dst; int idx;
    if (i < NX)            { src = X;  dst = Xr;  idx = i; }
    else if (i < NX + NW1) { src = W1; dst = W1r; idx = i - NX; }
    else if (i < NX + NW1 + NW2) { src = W2; dst = W2r; idx = i - NX - NW1; }
    else return;
    float4 v = src[idx];
    v.x = round_tf32(v.x); v.y = round_tf32(v.y);
    v.z = round_tf32(v.z); v.w = round_tf32(v.w);
    dst[idx] = v;
}

// ---------------------------------------------------------------------------
// tf32 mma.sync GEMM (NT): C = A @ W^T + bias. Inputs pre-rounded.
// CTA 128x256, warp 64x64, BK=32, 3-stage cp.async (R7 proven config).
// round_out != 0: round result to tf32 (feeds attention).
// ---------------------------------------------------------------------------
#define TM 128
#define TN 256
#define TK 32
#define NSTAGE 3
#define A_FLOATS (128 * 32)
#define B_FLOATS (256 * 32)
#define GEMM_SMEM (NSTAGE * (A_FLOATS + B_FLOATS) * 4)   // 144 KB

__global__ void __launch_bounds__(256, 1) gemm_mma(
    const float* __restrict__ A, const float* __restrict__ W,
    const float* __restrict__ bias, float* __restrict__ C,
    int M, int N, int K, int round_out)
{
    extern __shared__ float smem[];
    float* As = smem;                           // [NSTAGE][4096]
    float* Bs = smem + NSTAGE * A_FLOATS;       // [NSTAGE][8192]
    const uint32_t sA0 = s2u(As);
    const uint32_t sB0 = s2u(Bs);

    const int tid = threadIdx.x;
    const int wid = tid >> 5;
    const int lid = tid & 31;
    const int wm  = wid & 1;          // 2 warp rows -> 64 M
    const int wn  = wid >> 1;         // 4 warp cols -> 64 N
    const int g   = lid >> 2;
    const int t   = lid & 3;
    const int bm  = blockIdx.y * TM;
    const int bn  = blockIdx.x * TN;

    const int lrow = tid >> 3;        // 0..31
    const int lc4  = tid & 7;
    const uint32_t ldst = ((uint32_t)(lc4 ^ (lrow & 7))) * 16;

    float acc[4][8][4];
#pragma unroll
    for (int i = 0; i < 4; i++)
#pragma unroll
        for (int j = 0; j < 8; j++)
#pragma unroll
            for (int q = 0; q < 4; q++) acc[i][j][q] = 0.f;

    const int NCHUNK = K / TK;

#pragma unroll
    for (int p = 0; p < NSTAGE - 1; p++) {
        const float* Ag = A + (size_t)(bm + lrow) * K + p * TK + lc4 * 4;
        const float* Wg = W + (size_t)(bn + lrow) * K + p * TK + lc4 * 4;
        uint32_t dA = sA0 + p * (A_FLOATS * 4) + lrow * 128 + ldst;
        uint32_t dB = sB0 + p * (B_FLOATS * 4) + lrow * 128 + ldst;
#pragma unroll
        for (int r = 0; r < 4; r++)
            cp16(dA + r * (32 * 128), Ag + (size_t)(r * 32) * K);
#pragma unroll
        for (int r = 0; r < 8; r++)
            cp16(dB + r * (32 * 128), Wg + (size_t)(r * 32) * K);
        cp_commit();
    }

    const int swz = g << 2;

    for (int kc = 0; kc < NCHUNK; kc++) {
        cp_wait1();
        __syncthreads();

        const int s = kc % NSTAGE;
        const uint32_t* as = (const uint32_t*)(As + s * A_FLOATS + (wm * 64 + g) * 32);
        const uint32_t* bs = (const uint32_t*)(Bs + s * B_FLOATS + (wn * 64 + g) * 32);

#pragma unroll
        for (int kk = 0; kk < 4; kk++) {
            const int k0 = kk * 8;
            const int ck0 = (k0 + t) ^ swz;
            const int ck1 = (k0 + t + 4) ^ swz;

            uint32_t af[4][4];
#pragma unroll
            for (int i = 0; i < 4; i++) {
                const uint32_t* ai = as + i * (16 * 32);
                af[i][0] = ai[ck0];
                af[i][1] = ai[8 * 32 + ck0];
                af[i][2] = ai[ck1];
                af[i][3] = ai[8 * 32 + ck1];
            }
            uint32_t bf[8][2];
#pragma unroll
            for (int j = 0; j < 8; j++) {
                const uint32_t* bj = bs + j * (8 * 32);
                bf[j][0] = bj[ck0];
                bf[j][1] = bj[ck1];
            }
#pragma unroll
            for (int i = 0; i < 4; i++)
#pragma unroll
                for (int j = 0; j < 8; j++)
                    mma_tf32(acc[i][j][0], acc[i][j][1], acc[i][j][2], acc[i][j][3],
                             __uint_as_float(af[i][0]), __uint_as_float(af[i][1]),
                             __uint_as_float(af[i][2]), __uint_as_float(af[i][3]),
                             __uint_as_float(bf[j][0]), __uint_as_float(bf[j][1]));
        }

        const int nk = kc + NSTAGE - 1;
        if (nk < NCHUNK) {
            const int sn = nk % NSTAGE;
            const float* Ag = A + (size_t)(bm + lrow) * K + nk * TK + lc4 * 4;
            const float* Wg = W + (size_t)(bn + lrow) * K + nk * TK + lc4 * 4;
            uint32_t dA = sA0 + sn * (A_FLOATS * 4) + lrow * 128 + ldst;
            uint32_t dB = sB0 + sn * (B_FLOATS * 4) + lrow * 128 + ldst;
#pragma unroll
            for (int r = 0; r < 4; r++)
                cp16(dA + r * (32 * 128), Ag + (size_t)(r * 32) * K);
#pragma unroll
            for (int r = 0; r < 8; r++)
                cp16(dB + r * (32 * 128), Wg + (size_t)(r * 32) * K);
        }
        cp_commit();
    }

    // epilogue
#pragma unroll
    for (int i = 0; i < 4; i++) {
        const int row0 = bm + wm * 64 + i * 16 + g;
#pragma unroll
        for (int j = 0; j < 8; j++) {
            const int col = bn + wn * 64 + j * 8 + 2 * t;
            const float b0 = bias[col];
            const float b1 = bias[col + 1];
            float2 v0 = make_float2(acc[i][j][0] + b0, acc[i][j][1] + b1);
            float2 v1 = make_float2(acc[i][j][2] + b0, acc[i][j][3] + b1);
            if (round_out) {
                v0.x = round_tf32(v0.x); v0.y = round_tf32(v0.y);
                v1.x = round_tf32(v1.x); v1.y = round_tf32(v1.y);
            }
            *(float2*)&C[(size_t)row0 * N + col] = v0;
            *(float2*)&C[(size_t)(row0 + 8) * N + col] = v1;
        }
    }
}

// ---------------------------------------------------------------------------
// Attention stage A (tensor): partial scores. grid (64, NSPLIT).
// qkv already tf32-rounded -> staging is a pure copy.
// ---------------------------------------------------------------------------
#define PAD 68

__global__ void __launch_bounds__(256) attn_scores(
    const float* __restrict__ qkv, float* __restrict__ wp)
{
    __shared__ float sm[2 * 64 * PAD];
    float* S0 = sm;                 // Q chunk [s][d]
    float* S1 = sm + 64 * PAD;      // K chunk [s][e]

    const int bh = blockIdx.x;
    const int split = blockIdx.y;
    const int b  = bh >> 4;
    const int h  = bh & 15;
    const float* base = qkv + (size_t)b * S_ * (3 * D_);

    const int tid = threadIdx.x;
    const int wid = tid >> 5;
    const int lid = tid & 31;
    const int g   = lid >> 2;
    const int t   = lid & 3;
    const int wm  = wid & 3;        // 4 m-blocks of 16 -> 64 d
    const int wn  = wid >> 2;       // 2 n-blocks of 32 -> 64 e
    const int dA  = wm * 16 + g;
    const int nB  = wn * 32 + g;

    float acc[4][4];
#pragma unroll
    for (int j = 0; j < 4; j++)
#pragma unroll
        for (int q = 0; q < 4; q++) acc[j][q] = 0.f;

    const int sbeg = split * (S_ / NSPLIT);
    for (int s0 = sbeg; s0 < sbeg + S_ / NSPLIT; s0 += 64) {
#pragma unroll
        for (int jj = 0; jj < 4; jj++) {
            int l  = tid + jj * 256;
            int ss = l >> 4;
            int c4 = (l & 15) * 4;
            const float* gp = base + (size_t)(s0 + ss) * (3 * D_) + h * DH_ + c4;
            *(float4*)&S0[ss * PAD + c4] = *(const float4*)gp;
            *(float4*)&S1[ss * PAD + c4] = *(const float4*)(gp + D_);
        }
        __syncthreads();

#pragma unroll
        for (int ko = 0; ko < 8; ko++) {
            const int kr = ko * 8 + t;          // s index (contraction)
            float a0 = S0[kr * PAD + dA];
            float a1 = S0[kr * PAD + dA + 8];
            float a2 = S0[(kr + 4) * PAD + dA];
            float a3 = S0[(kr + 4) * PAD + dA + 8];
#pragma unroll
            for (int j = 0; j < 4; j++) {
                float b0 = S1[kr * PAD + nB + j * 8];
                float b1 = S1[(kr + 4) * PAD + nB + j * 8];
                mma_tf32(acc[j][0], acc[j][1], acc[j][2], acc[j][3],
                         a0, a1, a2, a3, b0, b1);
            }
        }
        __syncthreads();
    }

    float* wt = wp + ((size_t)(bh * NSPLIT + split)) * 4096;
    const int col0 = wn * 32 + 2 * t;
#pragma unroll
    for (int j = 0; j < 4; j++) {
        *(float2*)&wt[dA * 64 + col0 + j * 8]       = make_float2(acc[j][0], acc[j][1]);
        *(float2*)&wt[(dA + 8) * 64 + col0 + j * 8] = make_float2(acc[j][2], acc[j][3]);
    }
}

// ---------------------------------------------------------------------------
// Softmax: reduce NSPLIT partials (256 threads, parallel) + row softmax.
// grid 64 (bh), block 256.
// ---------------------------------------------------------------------------
__global__ void __launch_bounds__(256) attn_softmax(
    const float* __restrict__ wp, float* __restrict__ wf)
{
    __shared__ float sw[64 * PAD];
    const int bh = blockIdx.x;
    const int tid = threadIdx.x;
    const float* wt = wp + (size_t)bh * NSPLIT * 4096;
    const float scale = rsqrtf((float)S_);

    // phase 1: parallel reduce into smem (1024 float4 units over 256 threads)
    for (int l = tid; l < 1024; l += 256) {
        int d  = l >> 4;
        int e4 = (l & 15) * 4;
        float4 r = make_float4(0.f, 0.f, 0.f, 0.f);
#pragma unroll
        for (int p = 0; p < NSPLIT; p++) {
            float4 q = *(const float4*)&wt[(size_t)p * 4096 + d * 64 + e4];
            r.x += q.x; r.y += q.y; r.z += q.z; r.w += q.w;
        }
        r.x *= scale; r.y *= scale; r.z *= scale; r.w *= scale;
        *(float4*)&sw[d * PAD + e4] = r;
    }
    __syncthreads();

    // phase 2: per-row softmax (64 threads), tf32-rounded write to wf
    if (tid < 64) {
        float* row = &sw[tid * PAD];
        float m = -1e30f;
#pragma unroll
        for (int e = 0; e < 64; e++) m = fmaxf(m, row[e]);
        float s = 0.f;
#pragma unroll
        for (int e = 0; e < 64; e++) { float v = expf(row[e] - m); row[e] = v; s += v; }
        float inv = 1.f / s;
        float* wo = wf + (size_t)bh * 4096 + tid * 64;
#pragma unroll
        for (int e4 = 0; e4 < 16; e4++) {
            float4 v;
            v.x = round_tf32(row[e4 * 4 + 0] * inv);
            v.y = round_tf32(row[e4 * 4 + 1] * inv);
            v.z = round_tf32(row[e4 * 4 + 2] * inv);
            v.w = round_tf32(row[e4 * 4 + 3] * inv);
            *(float4*)&wo[e4 * 4] = v;
        }
    }
}

// ---------------------------------------------------------------------------
// Attention stage B (tensor): o = w @ V, scrambled store. grid (64, NSPLIT).
// ---------------------------------------------------------------------------
__global__ void __launch_bounds__(256) attn_out(
    const float* __restrict__ qkv, const float* __restrict__ wf,
    float* __restrict__ out)
{
    __shared__ float sm[2 * 64 * PAD];
    float* S0 = sm;                 // w (final)
    float* S1 = sm + 64 * PAD;      // V stage

    const int bh = blockIdx.x;
    const int split = blockIdx.y;
    const int b  = bh >> 4;
    const int h  = bh & 15;
    const float* base = qkv + (size_t)b * S_ * (3 * D_);

    const int tid = threadIdx.x;
    const int wid = tid >> 5;
    const int lid = tid & 31;
    const int g   = lid >> 2;
    const int t   = lid & 3;
    const int wm  = wid & 3;        // 4 m-blocks of 16 -> 64 d
    const int wn  = wid >> 2;       // 2 n-blocks of 32 -> 64 s per chunk

    // copy final w into smem (L2-hot, 16 KB)
    const float* wsrc = wf + (size_t)bh * 4096;
    for (int l = tid; l < 1024; l += 256) {
        int d  = l >> 4;
        int e4 = (l & 15) * 4;
        *(float4*)&S0[d * PAD + e4] = *(const float4*)&wsrc[d * 64 + e4];
    }
    __syncthreads();

    // hoist w fragments (constant across chunks): 32 regs
    float aw[8][4];
#pragma unroll
    for (int ko = 0; ko < 8; ko++) {
        const int kr = ko * 8 + t;              // e index (contraction)
        aw[ko][0] = S0[(wm * 16 + g) * PAD + kr];
        aw[ko][1] = S0[(wm * 16 + g + 8) * PAD + kr];
        aw[ko][2] = S0[(wm * 16 + g) * PAD + kr + 4];
        aw[ko][3] = S0[(wm * 16 + g + 8) * PAD + kr + 4];
    }

    const int sbeg = split * (S_ / NSPLIT);
    const int d  = wm * 16 + g;
    const int sl = wn * 32 + 2 * t;

    for (int s0 = sbeg; s0 < sbeg + S_ / NSPLIT; s0 += 64) {
#pragma unroll
        for (int jj = 0; jj < 4; jj++) {
            int l  = tid + jj * 256;
            int ss = l >> 4;
            int e4 = (l & 15) * 4;
            *(float4*)&S1[ss * PAD + e4] =
                *(const float4*)(base + (size_t)(s0 + ss) * (3 * D_) + 2 * D_ + h * DH_ + e4);
        }
        __syncthreads();

        float acc[4][4];
#pragma unroll
        for (int j = 0; j < 4; j++)
#pragma unroll
            for (int q = 0; q < 4; q++) acc[j][q] = 0.f;

#pragma unroll
        for (int ko = 0; ko < 8; ko++) {
            const int kr = ko * 8 + t;
#pragma unroll
            for (int j = 0; j < 4; j++) {
                const float* vr = &S1[(wn * 32 + j * 8 + g) * PAD];
                float b0 = vr[kr];
                float b1 = vr[kr + 4];
                mma_tf32(acc[j][0], acc[j][1], acc[j][2], acc[j][3],
                         aw[ko][0], aw[ko][1], aw[ko][2], aw[ko][3], b0, b1);
            }
        }
        __syncthreads();

        // scrambled store: out[b][h*128 + 2d + (s>>10)][s & 1023]
#pragma unroll
        for (int j = 0; j < 4; j++) {
            int s = s0 + sl + j * 8;
            int col = s & 1023;
            int hi  = s >> 10;
            size_t r0 = ((size_t)b * S_ + h * 128 + d * 2 + hi) * D_ + col;
            size_t r1 = ((size_t)b * S_ + h * 128 + (d + 8) * 2 + hi) * D_ + col;
            *(float2*)&out[r0] = make_float2(round_tf32(acc[j][0]), round_tf32(acc[j][1]));
            *(float2*)&out[r1] = make_float2(round_tf32(acc[j][2]), round_tf32(acc[j][3]));
        }
    }
}

// ---------------------------------------------------------------------------
extern "C" void kernel_launch(void* const* d_in, const int* in_sizes, int n_in,
                              void* d_out, int out_size)
{
    const float* X  = (const float*)d_in[0];
    const float* W1 = (const float*)d_in[1];
    const float* b1 = (const float*)d_in[2];
    const float* W2 = (const float*)d_in[3];
    const float* b2 = (const float*)d_in[4];
    float* out = (float*)d_out;

    float *qkv, *att, *Xr, *W1r, *W2r, *wp, *wf;
    cudaGetSymbolAddress((void**)&qkv, g_qkv);
    cudaGetSymbolAddress((void**)&att, g_att);
    cudaGetSymbolAddress((void**)&Xr,  g_Xr);
    cudaGetSymbolAddress((void**)&W1r, g_W1r);
    cudaGetSymbolAddress((void**)&W2r, g_W2r);
    cudaGetSymbolAddress((void**)&wp,  g_wp);
    cudaGetSymbolAddress((void**)&wf,  g_wf);

    cudaFuncSetAttribute(gemm_mma, cudaFuncAttributeMaxDynamicSharedMemorySize, GEMM_SMEM);

    // 0) pre-round inputs to tf32
    int total4 = NX + NW1 + NW2;
    round_inputs<<<(total4 + 255) / 256, 256>>>(
        (const float4*)X, (const float4*)W1, (const float4*)W2,
        (float4*)Xr, (float4*)W1r, (float4*)W2r);

    // 1) GEMM1: QKV = Xr @ W1r^T + b1, rounded to tf32   [8192, 3072]
    dim3 g1(3 * D_ / TN, (B_ * S_) / TM);
    gemm_mma<<<g1, 256, GEMM_SMEM>>>(Xr, W1r, b1, qkv, B_ * S_, 3 * D_, D_, 1);

    // 2) attention (tensor-core)
    attn_scores<<<dim3(B_ * H_, NSPLIT), 256>>>(qkv, wp);
    attn_softmax<<<B_ * H_, 256>>>(wp, wf);
    attn_out<<<dim3(B_ * H_, NSPLIT), 256>>>(qkv, wf, att);

    // 3) GEMM3: out = att @ W2r^T + b2  [8192, 1024]
    dim3 g3(D_ / TN, (B_ * S_) / TM);
    gemm_mma<<<g3, 256, GEMM_SMEM>>>(att, W2r, b2, out, B_ * S_, D_, D_, 0);
}